// round 14
// baseline (speedup 1.0000x reference)
#include <cuda_runtime.h>
#include <cuda_bf16.h>
#include <math.h>

#define Bb 32
#define Tt 64
#define Ss 256
#define Hh 512
#define Ee 256
#define Vv 32000
#define NHh 8
#define STEPS 63
#define NBLK2 296
#define NGRP 8
#define GRPSZ 37

// ---------------- scratch ----------------------------------------------------
#define O_KH   0
#define O_VH   (O_KH  + Bb*Ss*Hh)
#define O_H0   (O_VH  + Bb*Ss*Hh)
#define O_H1   (O_H0  + Bb*Hh)
#define O_H0P  (O_H1  + Bb*Hh)
#define O_Q    (O_H0P + Bb*Hh)
#define O_CTXR (O_Q   + Bb*Hh)
#define O_GH0  (O_CTXR+ 2*Bb*Hh)
#define O_GH1  (O_GH0 + Bb*3*Hh)
#define O_EG   (O_GH1 + Bb*3*Hh)
#define O_EMBA (O_EG  + STEPS*Bb*Ee)
#define O_GI0E (O_EMBA+ STEPS*Bb*Hh)
#define O_COMB (O_GI0E+ STEPS*Bb*3*Hh)
#define O_O1   (O_COMB+ STEPS*Bb*2*Hh)
#define O_TOTAL (O_O1 + STEPS*Bb*Hh)

__device__ float g_buf[O_TOTAL];
// hierarchical barrier state: 8 group counters / release words on separate 128B lines
__device__ unsigned g_cnt_arr[NGRP*32];
__device__ unsigned g_gen_arr[NGRP*32];
__device__ unsigned g_root[32];
__device__ __nv_bfloat16 g_whi[Vv*Hh];
__device__ __nv_bfloat16 g_wlo[Vv*Hh];
__device__ __nv_bfloat16 g_ahi[STEPS*Bb*Hh];
__device__ __nv_bfloat16 g_alo[STEPS*Bb*Hh];

__device__ __forceinline__ float clip100(float v){ return fminf(fmaxf(v,-100.f),100.f); }
__device__ __forceinline__ float sigm(float x){ return 1.f/(1.f+expf(-x)); }

// ---------------- setup kernels ----------------------------------------------
__global__ void init_kernel(const float* __restrict__ dec, const float* __restrict__ bo,
                            float* h0, float* h1, float* ctxr0){
    int i = blockIdx.x*256 + threadIdx.x;
    if (i < Bb*Hh){
        float v = fminf(fmaxf(dec[i], -10.f), 10.f);
        h0[i] = v; h1[i] = v;
        ctxr0[i] = bo[i & 511];
    }
}

__global__ void reset_kernel(){
    int i = blockIdx.x*256 + threadIdx.x;
    if (i < NGRP*32){ g_cnt_arr[i] = 0u; g_gen_arr[i] = 0u; }
    if (i < 32) g_root[i] = 0u;
}

__global__ void zero_kernel(float* __restrict__ out){
    int i = blockIdx.x*256 + threadIdx.x;
    if (i < Bb*Vv){
        int b = i / Vv, v = i % Vv;
        out[(size_t)b*Tt*Vv + v] = 0.f;
    }
}

__global__ void gather_emb_kernel(const int* __restrict__ tgt,
                                  const float* __restrict__ embt, float* __restrict__ Eg){
    int idx = blockIdx.x*256 + threadIdx.x;
    int row = idx >> 8, e = idx & 255;
    int t = row >> 5, b = row & 31;
    int tok = tgt[b*Tt + t];
    Eg[row*Ee + e] = embt[tok*Ee + e];
}

// fp32 -> bf16 hi/lo split
__global__ void conv_split_kernel(const float* __restrict__ src,
                                  __nv_bfloat16* __restrict__ hi,
                                  __nv_bfloat16* __restrict__ lo, int n){
    int i = blockIdx.x*256 + threadIdx.x;
    if (i < n){
        float v = src[i];
        __nv_bfloat16 h = __float2bfloat16(v);
        hi[i] = h;
        lo[i] = __float2bfloat16(v - __bfloat162float(h));
    }
}

// ---------------- big tiled SGEMM, double-buffered ----------------------------
// mode: 0 plain, 1 clip100, 2 relu;  ldw = row stride of W (>= K)
__global__ void gemm128_kernel(const float* __restrict__ A, const float* __restrict__ W,
                               const float* __restrict__ bias, float* __restrict__ C,
                               int M, int N, int K, int ldw, int mode){
    __shared__ float As[2][8][128];
    __shared__ float Ws[2][8][128];
    const int tid = threadIdx.x;
    const int bm = blockIdx.y * 128;
    const int bn = blockIdx.x * 128;
    const int lrow = tid >> 1;
    const int lk4  = (tid & 1) * 4;
    const int tx = tid & 15, ty = tid >> 4;

    float acc[8][8];
    #pragma unroll
    for (int i=0;i<8;i++)
        #pragma unroll
        for (int j=0;j<8;j++) acc[i][j]=0.f;

    float4 av, wv;
    auto ld = [&](int kb){
        av = make_float4(0.f,0.f,0.f,0.f);
        int ar = bm + lrow;
        if (ar < M) av = *(const float4*)(A + (size_t)ar*K + kb + lk4);
        wv = *(const float4*)(W + (size_t)(bn+lrow)*ldw + kb + lk4);
    };
    auto st = [&](int p){
        As[p][lk4+0][lrow]=av.x; As[p][lk4+1][lrow]=av.y;
        As[p][lk4+2][lrow]=av.z; As[p][lk4+3][lrow]=av.w;
        Ws[p][lk4+0][lrow]=wv.x; Ws[p][lk4+1][lrow]=wv.y;
        Ws[p][lk4+2][lrow]=wv.z; Ws[p][lk4+3][lrow]=wv.w;
    };

    ld(0); st(0);
    __syncthreads();
    int p = 0;
    for (int kb = 0; kb < K; kb += 8){
        if (kb + 8 < K) ld(kb + 8);
        #pragma unroll
        for (int k=0;k<8;k++){
            float4 a0 = *(const float4*)&As[p][k][ty*4];
            float4 a1 = *(const float4*)&As[p][k][64 + ty*4];
            float4 b0 = *(const float4*)&Ws[p][k][tx*4];
            float4 b1 = *(const float4*)&Ws[p][k][64 + tx*4];
            float am[8] = {a0.x,a0.y,a0.z,a0.w, a1.x,a1.y,a1.z,a1.w};
            float bm_[8]= {b0.x,b0.y,b0.z,b0.w, b1.x,b1.y,b1.z,b1.w};
            #pragma unroll
            for (int i=0;i<8;i++)
                #pragma unroll
                for (int j=0;j<8;j++)
                    acc[i][j] += am[i]*bm_[j];
        }
        if (kb + 8 < K) st(p ^ 1);
        __syncthreads();
        p ^= 1;
    }

    #pragma unroll
    for (int i=0;i<8;i++){
        int gm = bm + (i<4 ? ty*4+i : 64 + ty*4 + (i-4));
        if (gm >= M) continue;
        #pragma unroll
        for (int j=0;j<8;j++){
            int gn = bn + (j<4 ? tx*4+j : 64 + tx*4 + (j-4));
            float v = acc[i][j] + bias[gn];
            if (mode==1)      v = clip100(v);
            else if (mode==2) v = fmaxf(v, 0.f);
            C[(size_t)gm*N + gn] = v;
        }
    }
}

// ---------------- split-bf16 tensor-core vocab GEMM (128x128, cp.async) --------
#define MMA_BF16(cc, aa, bb) \
    asm volatile("mma.sync.aligned.m16n8k16.row.col.f32.bf16.bf16.f32 " \
        "{%0,%1,%2,%3},{%4,%5,%6,%7},{%8,%9},{%0,%1,%2,%3};" \
        : "+f"(cc[0]),"+f"(cc[1]),"+f"(cc[2]),"+f"(cc[3]) \
        : "r"(aa[0]),"r"(aa[1]),"r"(aa[2]),"r"(aa[3]), "r"(bb[0]),"r"(bb[1]))

#define VOCAB_SMEM (4*5120*2 + 4*5120*2)

__global__ void __launch_bounds__(256, 2) gemm_mma_vocab(
    const __nv_bfloat16* __restrict__ Ahi, const __nv_bfloat16* __restrict__ Alo,
    const __nv_bfloat16* __restrict__ Whi, const __nv_bfloat16* __restrict__ Wlo,
    const float* __restrict__ bias, float* __restrict__ out)
{
    extern __shared__ __nv_bfloat16 dsm[];
    const unsigned smem_u32 = (unsigned)__cvta_generic_to_shared(dsm);
    const int tid = threadIdx.x;
    const int lane = tid & 31, wid = tid >> 5;
    const int wm = wid & 1, wn = wid >> 1;
    const int g = lane >> 2, tg = lane & 3;
    const int bn = blockIdx.x * 128;
    const int bm = blockIdx.y * 128;

    float c[16][4];
    #pragma unroll
    for (int i=0;i<16;i++){ c[i][0]=0.f; c[i][1]=0.f; c[i][2]=0.f; c[i][3]=0.f; }

    const int row  = tid >> 1;
    const int h16  = (tid & 1) * 16;
    const int apred = ((bm + row) < STEPS*Bb) ? 16 : 0;

    auto cp16 = [&](unsigned dst, const void* src, int sz){
        asm volatile("cp.async.cg.shared.global [%0], [%1], 16, %2;"
                     :: "r"(dst), "l"(src), "r"(sz) : "memory");
    };
    auto cp_chunk = [&](int kb, int st){
        const size_t aoff = (size_t)(bm + row)*512 + kb + h16;
        unsigned da = smem_u32 + ((st*2+0)*5120 + row*40 + h16)*2;
        cp16(da,      Ahi + aoff,     apred);
        cp16(da + 16, Ahi + aoff + 8, apred);
        unsigned dal = da + 5120*2;
        cp16(dal,      Alo + aoff,     apred);
        cp16(dal + 16, Alo + aoff + 8, apred);
        const size_t woff = (size_t)(bn + row)*512 + kb + h16;
        unsigned dw = smem_u32 + (20480 + (st*2+0)*5120 + row*40 + h16)*2;
        cp16(dw,      Whi + woff,     16);
        cp16(dw + 16, Whi + woff + 8, 16);
        unsigned dwl = dw + 5120*2;
        cp16(dwl,      Wlo + woff,     16);
        cp16(dwl + 16, Wlo + woff + 8, 16);
        asm volatile("cp.async.commit_group;");
    };

    cp_chunk(0, 0);
    int st = 0;
    for (int kb = 0; kb < 512; kb += 32){
        if (kb + 32 < 512){
            cp_chunk(kb + 32, st ^ 1);
            asm volatile("cp.async.wait_group 1;");
        } else {
            asm volatile("cp.async.wait_group 0;");
        }
        __syncthreads();
        const __nv_bfloat16* A0 = dsm + (st*2+0)*5120;
        const __nv_bfloat16* A1 = dsm + (st*2+1)*5120;
        const __nv_bfloat16* W0 = dsm + 20480 + (st*2+0)*5120;
        const __nv_bfloat16* W1 = dsm + 20480 + (st*2+1)*5120;
        #pragma unroll
        for (int ko = 0; ko < 32; ko += 16){
            unsigned ah[4][4], al[4][4], bh[4][2], bl[4][2];
            const int c0 = ko + 2*tg, c8 = c0 + 8;
            #pragma unroll
            for (int mt=0; mt<4; mt++){
                int r0 = (wm*64 + mt*16 + g)*40;
                ah[mt][0] = *(const unsigned*)&A0[r0 + c0];
                ah[mt][1] = *(const unsigned*)&A0[r0 + 320 + c0];
                ah[mt][2] = *(const unsigned*)&A0[r0 + c8];
                ah[mt][3] = *(const unsigned*)&A0[r0 + 320 + c8];
                al[mt][0] = *(const unsigned*)&A1[r0 + c0];
                al[mt][1] = *(const unsigned*)&A1[r0 + 320 + c0];
                al[mt][2] = *(const unsigned*)&A1[r0 + c8];
                al[mt][3] = *(const unsigned*)&A1[r0 + 320 + c8];
            }
            #pragma unroll
            for (int nt=0; nt<4; nt++){
                int n0 = (wn*32 + nt*8 + g)*40;
                bh[nt][0] = *(const unsigned*)&W0[n0 + c0];
                bh[nt][1] = *(const unsigned*)&W0[n0 + c8];
                bl[nt][0] = *(const unsigned*)&W1[n0 + c0];
                bl[nt][1] = *(const unsigned*)&W1[n0 + c8];
            }
            #pragma unroll
            for (int mt=0; mt<4; mt++)
                #pragma unroll
                for (int nt=0; nt<4; nt++){
                    MMA_BF16(c[mt*4+nt], ah[mt], bh[nt]);
                    MMA_BF16(c[mt*4+nt], ah[mt], bl[nt]);
                    MMA_BF16(c[mt*4+nt], al[mt], bh[nt]);
                }
        }
        __syncthreads();
        st ^= 1;
    }
    #pragma unroll
    for (int nt=0; nt<4; nt++){
        int col = bn + wn*32 + nt*8 + 2*tg;
        float b0 = bias[col], b1 = bias[col+1];
        #pragma unroll
        for (int mt=0; mt<4; mt++){
            #pragma unroll
            for (int half=0; half<2; half++){
                int gm = bm + wm*64 + mt*16 + g + half*8;
                if (gm >= STEPS*Bb) continue;
                int bb2 = gm & 31, tt2 = gm >> 5;
                float v0 = clip100(c[mt*4+nt][half*2+0] + b0);
                float v1 = clip100(c[mt*4+nt][half*2+1] + b1);
                *(float2*)&out[((size_t)bb2*Tt + tt2 + 1)*Vv + col] = make_float2(v0, v1);
            }
        }
    }
}

// ---------------- persistent decoder loop -------------------------------------
struct SmemG { float As[32*132]; float Ws[32*128]; };
struct SmemA { float qs4[4][64]; float sc[256]; float red[64];
               float psum[4][64]; float ctxv[4][64]; };
union SmemU { SmemG g; SmemA a; };

struct Params {
    const int* mask;
    const float* wq;   const float* bq;
    const float* wo;   const float* bo;
    const float* w_ih0; const float* w_hh0; const float* b_ih0; const float* b_hh0;
    const float* w_ih1; const float* w_hh1; const float* b_ih1; const float* b_hh1;
    const float* Kh; const float* Vh; const float* gi0e;
    float *h0, *h1, *h0p, *q, *ctxr, *gh0, *gh1, *comb;
};

// hierarchical 2-level barrier: 8 group counters (<=37 arrivals each, parallel
// across LTS slices) -> root counter (8 arrivals) -> 8 replicated release words.
__device__ __forceinline__ void grid_bar(unsigned target){
    __syncthreads();
    if (threadIdx.x == 0){
        const int g = blockIdx.x & (NGRP-1);
        __threadfence();
        unsigned prev = atomicAdd(&g_cnt_arr[g*32], 1u);
        bool released = false;
        if (prev == target*GRPSZ - 1u){
            unsigned rprev = atomicAdd(&g_root[0], 1u);
            if (rprev == target*NGRP - 1u){
                __threadfence();
                #pragma unroll
                for (int i=0;i<NGRP;i++)
                    asm volatile("st.release.gpu.u32 [%0], %1;"
                                 :: "l"(&g_gen_arr[i*32]), "r"(target) : "memory");
                released = true;
            }
        }
        if (!released){
            unsigned v;
            do {
                asm volatile("ld.acquire.gpu.u32 %0, [%1];"
                             : "=r"(v) : "l"(&g_gen_arr[g*32]) : "memory");
            } while (v < target);
        }
    }
    __syncthreads();
}

__device__ __forceinline__ float block_max(float v, float* red){
    #pragma unroll
    for (int off=16; off>0; off>>=1) v = fmaxf(v, __shfl_xor_sync(0xffffffffu, v, off));
    if ((threadIdx.x & 31) == 0) red[threadIdx.x >> 5] = v;
    __syncthreads();
    if (threadIdx.x < 8){
        float x = red[threadIdx.x];
        #pragma unroll
        for (int off=4; off>0; off>>=1) x = fmaxf(x, __shfl_xor_sync(0xffu, x, off));
        if (threadIdx.x == 0) red[0] = x;
    }
    __syncthreads();
    float r = red[0];
    __syncthreads();
    return r;
}
__device__ __forceinline__ float block_sum(float v, float* red){
    #pragma unroll
    for (int off=16; off>0; off>>=1) v += __shfl_xor_sync(0xffffffffu, v, off);
    if ((threadIdx.x & 31) == 0) red[threadIdx.x >> 5] = v;
    __syncthreads();
    if (threadIdx.x < 8){
        float x = red[threadIdx.x];
        #pragma unroll
        for (int off=4; off>0; off>>=1) x += __shfl_xor_sync(0xffu, x, off);
        if (threadIdx.x == 0) red[0] = x;
    }
    __syncthreads();
    float r = red[0];
    __syncthreads();
    return r;
}

template<int NW>
__device__ void gemm_task(SmemU* sm, int n0, const float* __restrict__ A,
                          int K, const float* __restrict__ W, const float* __restrict__ bias,
                          float* __restrict__ C, int ldc, int act)
{
    const int tid = threadIdx.x;
    const int lane = tid & 31;
    const int wp = tid >> 5;
    float acc[NW];
    #pragma unroll
    for (int i=0;i<NW;i++) acc[i]=0.f;

    float4 pa[4];
    float4 pw[NW];
    auto loadA = [&](int kb){
        #pragma unroll
        for (int p2=0;p2<4;p2++){
            int idx = tid + p2*256;
            int r = idx >> 5, c4 = (idx & 31)*4;
            pa[p2] = *(const float4*)(A + r*512 + kb + c4);
        }
    };
    auto loadW = [&](int kb){
        #pragma unroll
        for (int q2=0;q2<NW;q2++){
            int idx = tid + q2*256;
            int n = idx >> 5, c4 = (idx & 31)*4;
            pw[q2] = *(const float4*)(W + (size_t)(n0+n)*K + kb + c4);
        }
    };

    loadA(0); loadW(0);
    for (int kb=0; kb<K; kb+=128){
        __syncthreads();
        #pragma unroll
        for (int p2=0;p2<4;p2++){
            int idx = tid + p2*256;
            int r = idx >> 5, c4 = (idx & 31)*4;
            *(float4*)&sm->g.As[r*132 + c4] = pa[p2];
        }
        #pragma unroll
        for (int q2=0;q2<NW;q2++){
            int idx = tid + q2*256;
            int n = idx >> 5, c4 = (idx & 31)*4;
            *(float4*)&sm->g.Ws[n*128 + c4] = pw[q2];
        }
        __syncthreads();
        if (kb + 128 < K){ loadA(kb+128); loadW(kb+128); }
        #pragma unroll
        for (int kc=0; kc<128; kc+=32){
            float a[32];
            #pragma unroll
            for (int j=0;j<32;j+=4)
                *(float4*)&a[j] = *(const float4*)&sm->g.As[lane*132 + kc + j];
            #pragma unroll
            for (int nn=0;nn<NW;nn++){
                const float* wr = &sm->g.Ws[(wp*NW+nn)*128 + kc];
                float s0=0.f, s1=0.f;
                #pragma unroll
                for (int j=0;j<32;j+=8){
                    float4 w0 = *(const float4*)(wr + j);
                    float4 w1 = *(const float4*)(wr + j + 4);
                    s0 += a[j+0]*w0.x + a[j+1]*w0.y + a[j+2]*w0.z + a[j+3]*w0.w;
                    s1 += a[j+4]*w1.x + a[j+5]*w1.y + a[j+6]*w1.z + a[j+7]*w1.w;
                }
                acc[nn] += s0 + s1;
            }
        }
    }
    #pragma unroll
    for (int nn=0;nn<NW;nn++){
        int n = n0 + wp*NW + nn;
        float v = acc[nn] + bias[n];
        if (act) v = clip100(v);
        C[lane*ldc + n] = v;
    }
}

// fused GEMM-triplet (K=512) + GRU nonlinearity.
template<bool CLIPA>
__device__ void gru_task(SmemU* sm, int n0, const float* __restrict__ A,
                         const float* __restrict__ W, int wstride, int woff,
                         const float* __restrict__ pre, const float* __restrict__ b_ih,
                         const float* __restrict__ gh,
                         float* __restrict__ hstate, float* __restrict__ hpre,
                         float* __restrict__ comb, const float* __restrict__ ctxr)
{
    const int tid = threadIdx.x;
    const int lane = tid & 31;
    const int wp = tid >> 5;
    float acc0=0.f, acc1=0.f, acc2=0.f;

    float4 pa[4];
    float4 pw[3];
    auto loadA = [&](int kb){
        #pragma unroll
        for (int p2=0;p2<4;p2++){
            int idx = tid + p2*256;
            int r = idx >> 5, c4 = (idx & 31)*4;
            float4 v = *(const float4*)(A + r*512 + kb + c4);
            if (CLIPA){
                v.x=clip100(v.x); v.y=clip100(v.y); v.z=clip100(v.z); v.w=clip100(v.w);
            }
            pa[p2] = v;
        }
    };
    auto loadW = [&](int kb){
        #pragma unroll
        for (int q2=0;q2<3;q2++){
            int idx = tid + q2*256;
            int nn = idx >> 5, c4 = (idx & 31)*4;
            int w = nn / 3, g = nn % 3;
            int grow = n0 + w + g*512;
            pw[q2] = *(const float4*)(W + (size_t)grow*wstride + woff + kb + c4);
        }
    };

    loadA(0); loadW(0);
    #pragma unroll
    for (int kb=0; kb<512; kb+=128){
        __syncthreads();
        #pragma unroll
        for (int p2=0;p2<4;p2++){
            int idx = tid + p2*256;
            int r = idx >> 5, c4 = (idx & 31)*4;
            *(float4*)&sm->g.As[r*132 + c4] = pa[p2];
        }
        #pragma unroll
        for (int q2=0;q2<3;q2++){
            int idx = tid + q2*256;
            int nn = idx >> 5, c4 = (idx & 31)*4;
            int w = nn / 3, g = nn % 3;
            *(float4*)&sm->g.Ws[(w*3+g)*128 + c4] = pw[q2];
        }
        __syncthreads();
        if (kb + 128 < 512){ loadA(kb+128); loadW(kb+128); }
        #pragma unroll
        for (int kc=0; kc<128; kc+=32){
            float a[32];
            #pragma unroll
            for (int j=0;j<32;j+=4)
                *(float4*)&a[j] = *(const float4*)&sm->g.As[lane*132 + kc + j];
            #pragma unroll
            for (int g=0; g<3; g++){
                const float* wr = &sm->g.Ws[(wp*3+g)*128 + kc];
                float s0=0.f, s1=0.f;
                #pragma unroll
                for (int j=0;j<32;j+=8){
                    float4 w0 = *(const float4*)(wr + j);
                    float4 w1 = *(const float4*)(wr + j + 4);
                    s0 += a[j+0]*w0.x + a[j+1]*w0.y + a[j+2]*w0.z + a[j+3]*w0.w;
                    s1 += a[j+4]*w1.x + a[j+5]*w1.y + a[j+6]*w1.z + a[j+7]*w1.w;
                }
                float s = s0 + s1;
                if (g==0) acc0 += s; else if (g==1) acc1 += s; else acc2 += s;
            }
        }
    }
    const int j = n0 + wp, b = lane;
    float pv0, pv1, pv2;
    if (pre){
        pv0 = pre[b*1536 + j];
        pv1 = pre[b*1536 + j + 512];
        pv2 = pre[b*1536 + j + 1024];
    } else {
        pv0 = b_ih[j]; pv1 = b_ih[j+512]; pv2 = b_ih[j+1024];
    }
    float ir = acc0 + pv0;
    float iz = acc1 + pv1;
    float in_ = acc2 + pv2;
    const int gg = b*1536 + j;
    float r = sigm(ir + gh[gg]);
    float z = sigm(iz + gh[gg+512]);
    float n = tanhf(in_ + r*gh[gg+1024]);
    float hv = (1.f - z)*n + z*hstate[b*512 + j];
    if (hpre) hpre[b*512 + j] = hv;
    hstate[b*512 + j] = fminf(fmaxf(hv, -10.f), 10.f);
    if (comb){
        comb[b*1024 + j]       = hv;
        comb[b*1024 + 512 + j] = clip100(ctxr[b*512 + j]);
    }
}

// attention core for (head h, batch group bg of 4), q precomputed
__device__ void attn_core(SmemU* smu, const Params& P, int h, int bg, float* ctxr){
    SmemA* sa = &smu->a;
    const int tid = threadIdx.x;
    {   int bi = tid >> 6, d = tid & 63;
        sa->qs4[bi][d] = P.q[(bg*4+bi)*512 + h*64 + d]; }
    __syncthreads();

    for (int bi=0; bi<4; bi++){
        const int b = bg*4 + bi;
        const float* kp = P.Kh + ((size_t)(b*256 + tid))*512 + h*64;
        const float* qv = sa->qs4[bi];
        float s = 0.f;
        #pragma unroll
        for (int d=0; d<64; d+=4){
            float4 kv = *(const float4*)(kp + d);
            s += qv[d]*kv.x + qv[d+1]*kv.y + qv[d+2]*kv.z + qv[d+3]*kv.w;
        }
        s *= 0.125f;
        if (P.mask[b*256 + tid] == 0) s = -10000.f;
        float mx = block_max(s, sa->red);
        float e = expf(s - mx);
        sa->sc[tid] = e;
        float inv = 1.f / block_sum(e, sa->red);
        __syncthreads();
        {
            int d = tid & 63, part = tid >> 6;
            const float* vp = P.Vh + ((size_t)(b*256))*512 + h*64 + d;
            float p0=0.f,p1=0.f,p2=0.f,p3=0.f,p4=0.f,p5=0.f,p6=0.f,p7=0.f;
            #pragma unroll 2
            for (int s2 = part*64; s2 < part*64 + 64; s2 += 8){
                p0 += sa->sc[s2]   * vp[(size_t)s2*512];
                p1 += sa->sc[s2+1] * vp[(size_t)(s2+1)*512];
                p2 += sa->sc[s2+2] * vp[(size_t)(s2+2)*512];
                p3 += sa->sc[s2+3] * vp[(size_t)(s2+3)*512];
                p4 += sa->sc[s2+4] * vp[(size_t)(s2+4)*512];
                p5 += sa->sc[s2+5] * vp[(size_t)(s2+5)*512];
                p6 += sa->sc[s2+6] * vp[(size_t)(s2+6)*512];
                p7 += sa->sc[s2+7] * vp[(size_t)(s2+7)*512];
            }
            sa->psum[part][d] = ((p0+p1)+(p2+p3)) + ((p4+p5)+(p6+p7));
        }
        __syncthreads();
        if (tid < 64)
            sa->ctxv[bi][tid] = (sa->psum[0][tid]+sa->psum[1][tid]
                               + sa->psum[2][tid]+sa->psum[3][tid]) * inv;
        __syncthreads();
    }
    #pragma unroll
    for (int rr=0; rr<2; rr++){
        int n = tid + rr*256;
        const float4* wr = (const float4*)(P.wo + (size_t)n*512 + h*64);
        float s0=0.f, s1=0.f, s2=0.f, s3=0.f;
        #pragma unroll
        for (int j=0;j<16;j++){
            float4 w = wr[j];
            const float* c0 = &sa->ctxv[0][j*4];
            const float* c1 = &sa->ctxv[1][j*4];
            const float* c2 = &sa->ctxv[2][j*4];
            const float* c3 = &sa->ctxv[3][j*4];
            s0 += c0[0]*w.x + c0[1]*w.y + c0[2]*w.z + c0[3]*w.w;
            s1 += c1[0]*w.x + c1[1]*w.y + c1[2]*w.z + c1[3]*w.w;
            s2 += c2[0]*w.x + c2[1]*w.y + c2[2]*w.z + c2[3]*w.w;
            s3 += c3[0]*w.x + c3[1]*w.y + c3[2]*w.z + c3[3]*w.w;
        }
        atomicAdd(ctxr + (bg*4+0)*512 + n, s0);
        atomicAdd(ctxr + (bg*4+1)*512 + n, s1);
        atomicAdd(ctxr + (bg*4+2)*512 + n, s2);
        atomicAdd(ctxr + (bg*4+3)*512 + n, s3);
    }
}

#define PHASE(nt_, ...)                                               \
    for (int ti = (int)blockIdx.x; ti < (nt_); ti += NBLK2){          \
        __syncthreads();                                              \
        __VA_ARGS__                                                   \
    }                                                                 \
    bar++; grid_bar(bar);

__global__ void __launch_bounds__(256, 2) decoder_loop_kernel(Params P){
    __shared__ SmemU sm;
    const int tid = threadIdx.x;
    unsigned bar = 0;

    for (int t = 0; t < STEPS; t++){
        float* ctxc = P.ctxr + (t & 1)*Bb*Hh;

        // P1: qproj x32 + gh1 x64 + ctx-init x8  (104 tasks)
        PHASE(104, {
            if (ti < 32){
                gemm_task<2>(&sm, ti*16, P.h1, 512, P.wq, P.bq, P.q, 512, 1);
            } else if (ti < 96){
                gemm_task<3>(&sm, (ti-32)*24, P.h1, 512, P.w_hh1, P.b_hh1, P.gh1, 1536, 0);
            } else {
                int base = (ti-96)*2048 + tid;
                #pragma unroll
                for (int e=0;e<8;e++){
                    int idx = base + e*256;
                    ctxc[idx] = P.bo[idx & 511];
                }
            }
        })
        // P2: attn x64 + gh0 x64  (128 tasks)
        PHASE(128, {
            if (ti < 64){
                attn_core(&sm, P, ti >> 3, ti & 7, ctxc);
            } else {
                gemm_task<3>(&sm, (ti-64)*24, P.h0, 512, P.w_hh0, P.b_hh0, P.gh0, 1536, 0);
            }
        })
        // P3: gi0(ctx half, K=512) + GRU0 fused  (64 tasks)
        PHASE(64, {
            gru_task<true>(&sm, ti*8, ctxc, P.w_ih0, 1024, 512,
                           P.gi0e + (size_t)t*Bb*3*Hh, nullptr,
                           P.gh0, P.h0, P.h0p, nullptr, nullptr);
        })
        // P4: gi1(K=512) + GRU1 fused + comb store  (64 tasks)
        PHASE(64, {
            gru_task<false>(&sm, ti*8, P.h0p, P.w_ih1, 512, 0,
                            nullptr, P.b_ih1,
                            P.gh1, P.h1, nullptr,
                            P.comb + (size_t)t*Bb*2*Hh, ctxc);
        })
    }
}

// ---------------- driver -------------------------------------------------------
extern "C" void kernel_launch(void* const* d_in, const int* in_sizes, int n_in,
                              void* d_out, int out_size){
    const int*   tgt   = (const int*)  d_in[0];
    const float* enc   = (const float*)d_in[1];
    const float* dec   = (const float*)d_in[2];
    const int*   mask  = (const int*)  d_in[3];
    const float* embt  = (const float*)d_in[4];
    const float* w_ep  = (const float*)d_in[5];
    const float* b_ep  = (const float*)d_in[6];
    const float* wq    = (const float*)d_in[7];
    const float* bq    = (const float*)d_in[8];
    const float* wk    = (const float*)d_in[9];
    const float* bk    = (const float*)d_in[10];
    const float* wv    = (const float*)d_in[11];
    const float* bv    = (const float*)d_in[12];
    const float* wo    = (const float*)d_in[13];
    const float* bo    = (const float*)d_in[14];
    const float* w_ih0 = (const float*)d_in[15];
    const float* w_hh0 = (const float*)d_in[16];
    const float* b_ih0 = (const float*)d_in[17];
    const float* b_hh0 = (const float*)d_in[18];
    const float* w_ih1 = (const float*)d_in[19];
    const float* w_hh1 = (const float*)d_in[20];
    const float* b_ih1 = (const float*)d_in[21];
    const float* b_hh1 = (const float*)d_in[22];
    const float* w_o1  = (const float*)d_in[23];
    const float* b_o1  = (const float*)d_in[24];
    const float* w_o2  = (const float*)d_in[25];
    const float* b_o2  = (const float*)d_in[26];
    float* out = (float*)d_out;

    float* buf = nullptr;
    cudaGetSymbolAddress((void**)&buf, g_buf);
    __nv_bfloat16 *whi, *wlo, *ahi, *alo;
    cudaGetSymbolAddress((void**)&whi, g_whi);
    cudaGetSymbolAddress((void**)&wlo, g_wlo);
    cudaGetSymbolAddress((void**)&ahi, g_ahi);
    cudaGetSymbolAddress((void**)&alo, g_alo);

    Params P;
    P.mask = mask;
    P.wq = wq; P.bq = bq; P.wo = wo; P.bo = bo;
    P.w_ih0 = w_ih0; P.w_hh0 = w_hh0; P.b_ih0 = b_ih0; P.b_hh0 = b_hh0;
    P.w_ih1 = w_ih1; P.w_hh1 = w_hh1; P.b_ih1 = b_ih1; P.b_hh1 = b_hh1;
    P.Kh = buf + O_KH; P.Vh = buf + O_VH;
    P.h0 = buf + O_H0; P.h1 = buf + O_H1; P.h0p = buf + O_H0P;
    P.q = buf + O_Q; P.ctxr = buf + O_CTXR;
    P.gh0 = buf + O_GH0; P.gh1 = buf + O_GH1;
    P.gi0e = buf + O_GI0E;
    P.comb = buf + O_COMB;
    float* Eg = buf + O_EG;
    float* emba = buf + O_EMBA;
    float* o1 = buf + O_O1;

    reset_kernel<<<1, 256>>>();
    init_kernel<<<(Bb*Hh+255)/256, 256>>>(dec, bo, P.h0, P.h1, P.ctxr);
    zero_kernel<<<(Bb*Vv+255)/256, 256>>>(out);

    // one-time: split w_o2 into bf16 hi/lo
    conv_split_kernel<<<(Vv*Hh+255)/256, 256>>>(w_o2, whi, wlo, Vv*Hh);

    // hoisted: embedding gather + projection for all 63 steps
    gather_emb_kernel<<<(STEPS*Bb*Ee)/256, 256>>>(tgt, embt, Eg);
    gemm128_kernel<<<dim3(Hh/128, (STEPS*Bb+127)/128), 256>>>(
        Eg, w_ep, b_ep, emba, STEPS*Bb, Hh, Ee, Ee, 0);
    // hoisted: emb half of gi0 for all steps
    gemm128_kernel<<<dim3((3*Hh)/128, (STEPS*Bb+127)/128), 256>>>(
        emba, w_ih0, b_ih0, (float*)P.gi0e, STEPS*Bb, 3*Hh, Hh, 2*Hh, 0);

    // step-invariant K/V projections (Kh clipped, Vh plain)
    gemm128_kernel<<<dim3(Hh/128, (Bb*Ss)/128), 256>>>(enc, wk, bk, (float*)P.Kh, Bb*Ss, Hh, Hh, Hh, 1);
    gemm128_kernel<<<dim3(Hh/128, (Bb*Ss)/128), 256>>>(enc, wv, bv, (float*)P.Vh, Bb*Ss, Hh, Hh, Hh, 0);

    // full 63-step recurrence, 4 hierarchical grid barriers per step
    decoder_loop_kernel<<<NBLK2, 256>>>(P);

    // batched output MLP: o1 = relu(comb @ w_o1^T + b_o1)  (fp32)
    gemm128_kernel<<<dim3(Hh/128, (STEPS*Bb+127)/128), 256>>>(
        P.comb, w_o1, b_o1, o1, STEPS*Bb, Hh, 2*Hh, 2*Hh, 2);
    // split o1 into bf16 hi/lo, then tensor-core vocab GEMM (128x128 tiles)
    conv_split_kernel<<<(STEPS*Bb*Hh+255)/256, 256>>>(o1, ahi, alo, STEPS*Bb*Hh);
    cudaFuncSetAttribute(gemm_mma_vocab, cudaFuncAttributeMaxDynamicSharedMemorySize, VOCAB_SMEM);
    gemm_mma_vocab<<<dim3(Vv/128, 16), 256, VOCAB_SMEM>>>(ahi, alo, whi, wlo, b_o2, out);
}

// round 15
// speedup vs baseline: 1.3315x; 1.3315x over previous
#include <cuda_runtime.h>
#include <cuda_bf16.h>
#include <math.h>

#define Bb 32
#define Tt 64
#define Ss 256
#define Hh 512
#define Ee 256
#define Vv 32000
#define NHh 8
#define STEPS 63
#define NBLK2 296

// ---------------- scratch ----------------------------------------------------
#define O_KH   0
#define O_VH   (O_KH  + Bb*Ss*Hh)
#define O_H0   (O_VH  + Bb*Ss*Hh)
#define O_H1   (O_H0  + Bb*Hh)
#define O_H0P  (O_H1  + Bb*Hh)
#define O_Q    (O_H0P + Bb*Hh)
#define O_CTXR (O_Q   + Bb*Hh)
#define O_GH0  (O_CTXR+ 2*Bb*Hh)
#define O_GH1  (O_GH0 + Bb*3*Hh)
#define O_EG   (O_GH1 + Bb*3*Hh)
#define O_EMBA (O_EG  + STEPS*Bb*Ee)
#define O_GI0E (O_EMBA+ STEPS*Bb*Hh)
#define O_COMB (O_GI0E+ STEPS*Bb*3*Hh)
#define O_O1   (O_COMB+ STEPS*Bb*2*Hh)
#define O_TOTAL (O_O1 + STEPS*Bb*Hh)

__device__ float g_buf[O_TOTAL];
__device__ unsigned g_cnt_arr[64];
__device__ unsigned g_gen_arr[64];
__device__ __nv_bfloat16 g_whi[Vv*Hh];
__device__ __nv_bfloat16 g_wlo[Vv*Hh];
__device__ __nv_bfloat16 g_ahi[STEPS*Bb*Hh];
__device__ __nv_bfloat16 g_alo[STEPS*Bb*Hh];

__device__ __forceinline__ float clip100(float v){ return fminf(fmaxf(v,-100.f),100.f); }
__device__ __forceinline__ float sigm(float x){ return 1.f/(1.f+expf(-x)); }

// ---------------- setup kernels ----------------------------------------------
__global__ void init_kernel(const float* __restrict__ dec, const float* __restrict__ bo,
                            float* h0, float* h1, float* ctxr0){
    int i = blockIdx.x*256 + threadIdx.x;
    if (i < Bb*Hh){
        float v = fminf(fmaxf(dec[i], -10.f), 10.f);
        h0[i] = v; h1[i] = v;
        ctxr0[i] = bo[i & 511];
    }
}

__global__ void reset_kernel(){
    if (threadIdx.x == 0 && blockIdx.x == 0){ g_cnt_arr[0] = 0u; g_gen_arr[0] = 0u; }
}

__global__ void zero_kernel(float* __restrict__ out){
    int i = blockIdx.x*256 + threadIdx.x;
    if (i < Bb*Vv){
        int b = i / Vv, v = i % Vv;
        out[(size_t)b*Tt*Vv + v] = 0.f;
    }
}

__global__ void gather_emb_kernel(const int* __restrict__ tgt,
                                  const float* __restrict__ embt, float* __restrict__ Eg){
    int idx = blockIdx.x*256 + threadIdx.x;
    int row = idx >> 8, e = idx & 255;
    int t = row >> 5, b = row & 31;
    int tok = tgt[b*Tt + t];
    Eg[row*Ee + e] = embt[tok*Ee + e];
}

// fp32 -> bf16 hi/lo split
__global__ void conv_split_kernel(const float* __restrict__ src,
                                  __nv_bfloat16* __restrict__ hi,
                                  __nv_bfloat16* __restrict__ lo, int n){
    int i = blockIdx.x*256 + threadIdx.x;
    if (i < n){
        float v = src[i];
        __nv_bfloat16 h = __float2bfloat16(v);
        hi[i] = h;
        lo[i] = __float2bfloat16(v - __bfloat162float(h));
    }
}

// ---------------- big tiled SGEMM, double-buffered ----------------------------
// mode: 0 plain, 1 clip100, 2 relu;  ldw = row stride of W (>= K)
__global__ void gemm128_kernel(const float* __restrict__ A, const float* __restrict__ W,
                               const float* __restrict__ bias, float* __restrict__ C,
                               int M, int N, int K, int ldw, int mode){
    __shared__ float As[2][8][128];
    __shared__ float Ws[2][8][128];
    const int tid = threadIdx.x;
    const int bm = blockIdx.y * 128;
    const int bn = blockIdx.x * 128;
    const int lrow = tid >> 1;
    const int lk4  = (tid & 1) * 4;
    const int tx = tid & 15, ty = tid >> 4;

    float acc[8][8];
    #pragma unroll
    for (int i=0;i<8;i++)
        #pragma unroll
        for (int j=0;j<8;j++) acc[i][j]=0.f;

    float4 av, wv;
    auto ld = [&](int kb){
        av = make_float4(0.f,0.f,0.f,0.f);
        int ar = bm + lrow;
        if (ar < M) av = *(const float4*)(A + (size_t)ar*K + kb + lk4);
        wv = *(const float4*)(W + (size_t)(bn+lrow)*ldw + kb + lk4);
    };
    auto st = [&](int p){
        As[p][lk4+0][lrow]=av.x; As[p][lk4+1][lrow]=av.y;
        As[p][lk4+2][lrow]=av.z; As[p][lk4+3][lrow]=av.w;
        Ws[p][lk4+0][lrow]=wv.x; Ws[p][lk4+1][lrow]=wv.y;
        Ws[p][lk4+2][lrow]=wv.z; Ws[p][lk4+3][lrow]=wv.w;
    };

    ld(0); st(0);
    __syncthreads();
    int p = 0;
    for (int kb = 0; kb < K; kb += 8){
        if (kb + 8 < K) ld(kb + 8);
        #pragma unroll
        for (int k=0;k<8;k++){
            float4 a0 = *(const float4*)&As[p][k][ty*4];
            float4 a1 = *(const float4*)&As[p][k][64 + ty*4];
            float4 b0 = *(const float4*)&Ws[p][k][tx*4];
            float4 b1 = *(const float4*)&Ws[p][k][64 + tx*4];
            float am[8] = {a0.x,a0.y,a0.z,a0.w, a1.x,a1.y,a1.z,a1.w};
            float bm_[8]= {b0.x,b0.y,b0.z,b0.w, b1.x,b1.y,b1.z,b1.w};
            #pragma unroll
            for (int i=0;i<8;i++)
                #pragma unroll
                for (int j=0;j<8;j++)
                    acc[i][j] += am[i]*bm_[j];
        }
        if (kb + 8 < K) st(p ^ 1);
        __syncthreads();
        p ^= 1;
    }

    #pragma unroll
    for (int i=0;i<8;i++){
        int gm = bm + (i<4 ? ty*4+i : 64 + ty*4 + (i-4));
        if (gm >= M) continue;
        #pragma unroll
        for (int j=0;j<8;j++){
            int gn = bn + (j<4 ? tx*4+j : 64 + tx*4 + (j-4));
            float v = acc[i][j] + bias[gn];
            if (mode==1)      v = clip100(v);
            else if (mode==2) v = fmaxf(v, 0.f);
            C[(size_t)gm*N + gn] = v;
        }
    }
}

// ---------------- split-bf16 tensor-core vocab GEMM (128x128, cp.async) --------
#define MMA_BF16(cc, aa, bb) \
    asm volatile("mma.sync.aligned.m16n8k16.row.col.f32.bf16.bf16.f32 " \
        "{%0,%1,%2,%3},{%4,%5,%6,%7},{%8,%9},{%0,%1,%2,%3};" \
        : "+f"(cc[0]),"+f"(cc[1]),"+f"(cc[2]),"+f"(cc[3]) \
        : "r"(aa[0]),"r"(aa[1]),"r"(aa[2]),"r"(aa[3]), "r"(bb[0]),"r"(bb[1]))

#define VOCAB_SMEM (4*5120*2 + 4*5120*2)

__global__ void __launch_bounds__(256, 2) gemm_mma_vocab(
    const __nv_bfloat16* __restrict__ Ahi, const __nv_bfloat16* __restrict__ Alo,
    const __nv_bfloat16* __restrict__ Whi, const __nv_bfloat16* __restrict__ Wlo,
    const float* __restrict__ bias, float* __restrict__ out)
{
    extern __shared__ __nv_bfloat16 dsm[];
    const unsigned smem_u32 = (unsigned)__cvta_generic_to_shared(dsm);
    const int tid = threadIdx.x;
    const int lane = tid & 31, wid = tid >> 5;
    const int wm = wid & 1, wn = wid >> 1;
    const int g = lane >> 2, tg = lane & 3;
    const int bn = blockIdx.x * 128;
    const int bm = blockIdx.y * 128;

    float c[16][4];
    #pragma unroll
    for (int i=0;i<16;i++){ c[i][0]=0.f; c[i][1]=0.f; c[i][2]=0.f; c[i][3]=0.f; }

    const int row  = tid >> 1;
    const int h16  = (tid & 1) * 16;
    const int apred = ((bm + row) < STEPS*Bb) ? 16 : 0;

    auto cp16 = [&](unsigned dst, const void* src, int sz){
        asm volatile("cp.async.cg.shared.global [%0], [%1], 16, %2;"
                     :: "r"(dst), "l"(src), "r"(sz) : "memory");
    };
    auto cp_chunk = [&](int kb, int st){
        const size_t aoff = (size_t)(bm + row)*512 + kb + h16;
        unsigned da = smem_u32 + ((st*2+0)*5120 + row*40 + h16)*2;
        cp16(da,      Ahi + aoff,     apred);
        cp16(da + 16, Ahi + aoff + 8, apred);
        unsigned dal = da + 5120*2;
        cp16(dal,      Alo + aoff,     apred);
        cp16(dal + 16, Alo + aoff + 8, apred);
        const size_t woff = (size_t)(bn + row)*512 + kb + h16;
        unsigned dw = smem_u32 + (20480 + (st*2+0)*5120 + row*40 + h16)*2;
        cp16(dw,      Whi + woff,     16);
        cp16(dw + 16, Whi + woff + 8, 16);
        unsigned dwl = dw + 5120*2;
        cp16(dwl,      Wlo + woff,     16);
        cp16(dwl + 16, Wlo + woff + 8, 16);
        asm volatile("cp.async.commit_group;");
    };

    cp_chunk(0, 0);
    int st = 0;
    for (int kb = 0; kb < 512; kb += 32){
        if (kb + 32 < 512){
            cp_chunk(kb + 32, st ^ 1);
            asm volatile("cp.async.wait_group 1;");
        } else {
            asm volatile("cp.async.wait_group 0;");
        }
        __syncthreads();
        const __nv_bfloat16* A0 = dsm + (st*2+0)*5120;
        const __nv_bfloat16* A1 = dsm + (st*2+1)*5120;
        const __nv_bfloat16* W0 = dsm + 20480 + (st*2+0)*5120;
        const __nv_bfloat16* W1 = dsm + 20480 + (st*2+1)*5120;
        #pragma unroll
        for (int ko = 0; ko < 32; ko += 16){
            unsigned ah[4][4], al[4][4], bh[4][2], bl[4][2];
            const int c0 = ko + 2*tg, c8 = c0 + 8;
            #pragma unroll
            for (int mt=0; mt<4; mt++){
                int r0 = (wm*64 + mt*16 + g)*40;
                ah[mt][0] = *(const unsigned*)&A0[r0 + c0];
                ah[mt][1] = *(const unsigned*)&A0[r0 + 320 + c0];
                ah[mt][2] = *(const unsigned*)&A0[r0 + c8];
                ah[mt][3] = *(const unsigned*)&A0[r0 + 320 + c8];
                al[mt][0] = *(const unsigned*)&A1[r0 + c0];
                al[mt][1] = *(const unsigned*)&A1[r0 + 320 + c0];
                al[mt][2] = *(const unsigned*)&A1[r0 + c8];
                al[mt][3] = *(const unsigned*)&A1[r0 + 320 + c8];
            }
            #pragma unroll
            for (int nt=0; nt<4; nt++){
                int n0 = (wn*32 + nt*8 + g)*40;
                bh[nt][0] = *(const unsigned*)&W0[n0 + c0];
                bh[nt][1] = *(const unsigned*)&W0[n0 + c8];
                bl[nt][0] = *(const unsigned*)&W1[n0 + c0];
                bl[nt][1] = *(const unsigned*)&W1[n0 + c8];
            }
            #pragma unroll
            for (int mt=0; mt<4; mt++)
                #pragma unroll
                for (int nt=0; nt<4; nt++){
                    MMA_BF16(c[mt*4+nt], ah[mt], bh[nt]);
                    MMA_BF16(c[mt*4+nt], ah[mt], bl[nt]);
                    MMA_BF16(c[mt*4+nt], al[mt], bh[nt]);
                }
        }
        __syncthreads();
        st ^= 1;
    }
    #pragma unroll
    for (int nt=0; nt<4; nt++){
        int col = bn + wn*32 + nt*8 + 2*tg;
        float b0 = bias[col], b1 = bias[col+1];
        #pragma unroll
        for (int mt=0; mt<4; mt++){
            #pragma unroll
            for (int half=0; half<2; half++){
                int gm = bm + wm*64 + mt*16 + g + half*8;
                if (gm >= STEPS*Bb) continue;
                int bb2 = gm & 31, tt2 = gm >> 5;
                float v0 = clip100(c[mt*4+nt][half*2+0] + b0);
                float v1 = clip100(c[mt*4+nt][half*2+1] + b1);
                *(float2*)&out[((size_t)bb2*Tt + tt2 + 1)*Vv + col] = make_float2(v0, v1);
            }
        }
    }
}

// ---------------- persistent decoder loop -------------------------------------
struct SmemG { float As[32*132]; float Ws[32*128]; };
struct SmemA { float qs2[2][64]; float sc[256]; float red[64];
               float psum[4][64]; float ctxv[2][64]; };
union SmemU { SmemG g; SmemA a; };

struct Params {
    const int* mask;
    const float* wq;   const float* bq;
    const float* wo;   const float* bo;
    const float* w_ih0; const float* w_hh0; const float* b_ih0; const float* b_hh0;
    const float* w_ih1; const float* w_hh1; const float* b_ih1; const float* b_hh1;
    const float* Kh; const float* Vh; const float* gi0e;
    float *h0, *h1, *h0p, *q, *ctxr, *gh0, *gh1, *comb;
};

// flat counter barrier (best measured, R13)
__device__ __forceinline__ void grid_bar(unsigned target){
    __syncthreads();
    if (threadIdx.x == 0){
        __threadfence();
        unsigned prev = atomicAdd(&g_cnt_arr[0], 1u);
        if (prev == target*NBLK2 - 1u){
            __threadfence();
            asm volatile("st.release.gpu.u32 [%0], %1;" :: "l"(&g_gen_arr[0]), "r"(target) : "memory");
        } else {
            unsigned v;
            do {
                asm volatile("ld.acquire.gpu.u32 %0, [%1];" : "=r"(v) : "l"(&g_gen_arr[0]) : "memory");
            } while (v < target);
        }
    }
    __syncthreads();
}

__device__ __forceinline__ float block_max(float v, float* red){
    #pragma unroll
    for (int off=16; off>0; off>>=1) v = fmaxf(v, __shfl_xor_sync(0xffffffffu, v, off));
    if ((threadIdx.x & 31) == 0) red[threadIdx.x >> 5] = v;
    __syncthreads();
    if (threadIdx.x < 8){
        float x = red[threadIdx.x];
        #pragma unroll
        for (int off=4; off>0; off>>=1) x = fmaxf(x, __shfl_xor_sync(0xffu, x, off));
        if (threadIdx.x == 0) red[0] = x;
    }
    __syncthreads();
    float r = red[0];
    __syncthreads();
    return r;
}
__device__ __forceinline__ float block_sum(float v, float* red){
    #pragma unroll
    for (int off=16; off>0; off>>=1) v += __shfl_xor_sync(0xffffffffu, v, off);
    if ((threadIdx.x & 31) == 0) red[threadIdx.x >> 5] = v;
    __syncthreads();
    if (threadIdx.x < 8){
        float x = red[threadIdx.x];
        #pragma unroll
        for (int off=4; off>0; off>>=1) x += __shfl_xor_sync(0xffu, x, off);
        if (threadIdx.x == 0) red[0] = x;
    }
    __syncthreads();
    float r = red[0];
    __syncthreads();
    return r;
}

template<int NW>
__device__ void gemm_task(SmemU* sm, int n0, const float* __restrict__ A,
                          int K, const float* __restrict__ W, const float* __restrict__ bias,
                          float* __restrict__ C, int ldc, int act)
{
    const int tid = threadIdx.x;
    const int lane = tid & 31;
    const int wp = tid >> 5;
    float acc[NW];
    #pragma unroll
    for (int i=0;i<NW;i++) acc[i]=0.f;

    float4 pa[4];
    float4 pw[NW];
    auto loadA = [&](int kb){
        #pragma unroll
        for (int p2=0;p2<4;p2++){
            int idx = tid + p2*256;
            int r = idx >> 5, c4 = (idx & 31)*4;
            pa[p2] = *(const float4*)(A + r*512 + kb + c4);
        }
    };
    auto loadW = [&](int kb){
        #pragma unroll
        for (int q2=0;q2<NW;q2++){
            int idx = tid + q2*256;
            int n = idx >> 5, c4 = (idx & 31)*4;
            pw[q2] = *(const float4*)(W + (size_t)(n0+n)*K + kb + c4);
        }
    };

    loadA(0); loadW(0);
    for (int kb=0; kb<K; kb+=128){
        __syncthreads();
        #pragma unroll
        for (int p2=0;p2<4;p2++){
            int idx = tid + p2*256;
            int r = idx >> 5, c4 = (idx & 31)*4;
            *(float4*)&sm->g.As[r*132 + c4] = pa[p2];
        }
        #pragma unroll
        for (int q2=0;q2<NW;q2++){
            int idx = tid + q2*256;
            int n = idx >> 5, c4 = (idx & 31)*4;
            *(float4*)&sm->g.Ws[n*128 + c4] = pw[q2];
        }
        __syncthreads();
        if (kb + 128 < K){ loadA(kb+128); loadW(kb+128); }
        #pragma unroll
        for (int kc=0; kc<128; kc+=32){
            float a[32];
            #pragma unroll
            for (int j=0;j<32;j+=4)
                *(float4*)&a[j] = *(const float4*)&sm->g.As[lane*132 + kc + j];
            #pragma unroll
            for (int nn=0;nn<NW;nn++){
                const float* wr = &sm->g.Ws[(wp*NW+nn)*128 + kc];
                float s0=0.f, s1=0.f;
                #pragma unroll
                for (int j=0;j<32;j+=8){
                    float4 w0 = *(const float4*)(wr + j);
                    float4 w1 = *(const float4*)(wr + j + 4);
                    s0 += a[j+0]*w0.x + a[j+1]*w0.y + a[j+2]*w0.z + a[j+3]*w0.w;
                    s1 += a[j+4]*w1.x + a[j+5]*w1.y + a[j+6]*w1.z + a[j+7]*w1.w;
                }
                acc[nn] += s0 + s1;
            }
        }
    }
    #pragma unroll
    for (int nn=0;nn<NW;nn++){
        int n = n0 + wp*NW + nn;
        float v = acc[nn] + bias[n];
        if (act) v = clip100(v);
        C[lane*ldc + n] = v;
    }
}

// fused GEMM-triplet (K=512) + GRU nonlinearity.
template<bool CLIPA>
__device__ void gru_task(SmemU* sm, int n0, const float* __restrict__ A,
                         const float* __restrict__ W, int wstride, int woff,
                         const float* __restrict__ pre, const float* __restrict__ b_ih,
                         const float* __restrict__ gh,
                         float* __restrict__ hstate, float* __restrict__ hpre,
                         float* __restrict__ comb, const float* __restrict__ ctxr)
{
    const int tid = threadIdx.x;
    const int lane = tid & 31;
    const int wp = tid >> 5;
    float acc0=0.f, acc1=0.f, acc2=0.f;

    float4 pa[4];
    float4 pw[3];
    auto loadA = [&](int kb){
        #pragma unroll
        for (int p2=0;p2<4;p2++){
            int idx = tid + p2*256;
            int r = idx >> 5, c4 = (idx & 31)*4;
            float4 v = *(const float4*)(A + r*512 + kb + c4);
            if (CLIPA){
                v.x=clip100(v.x); v.y=clip100(v.y); v.z=clip100(v.z); v.w=clip100(v.w);
            }
            pa[p2] = v;
        }
    };
    auto loadW = [&](int kb){
        #pragma unroll
        for (int q2=0;q2<3;q2++){
            int idx = tid + q2*256;
            int nn = idx >> 5, c4 = (idx & 31)*4;
            int w = nn / 3, g = nn % 3;
            int grow = n0 + w + g*512;
            pw[q2] = *(const float4*)(W + (size_t)grow*wstride + woff + kb + c4);
        }
    };

    loadA(0); loadW(0);
    #pragma unroll
    for (int kb=0; kb<512; kb+=128){
        __syncthreads();
        #pragma unroll
        for (int p2=0;p2<4;p2++){
            int idx = tid + p2*256;
            int r = idx >> 5, c4 = (idx & 31)*4;
            *(float4*)&sm->g.As[r*132 + c4] = pa[p2];
        }
        #pragma unroll
        for (int q2=0;q2<3;q2++){
            int idx = tid + q2*256;
            int nn = idx >> 5, c4 = (idx & 31)*4;
            int w = nn / 3, g = nn % 3;
            *(float4*)&sm->g.Ws[(w*3+g)*128 + c4] = pw[q2];
        }
        __syncthreads();
        if (kb + 128 < 512){ loadA(kb+128); loadW(kb+128); }
        #pragma unroll
        for (int kc=0; kc<128; kc+=32){
            float a[32];
            #pragma unroll
            for (int j=0;j<32;j+=4)
                *(float4*)&a[j] = *(const float4*)&sm->g.As[lane*132 + kc + j];
            #pragma unroll
            for (int g=0; g<3; g++){
                const float* wr = &sm->g.Ws[(wp*3+g)*128 + kc];
                float s0=0.f, s1=0.f;
                #pragma unroll
                for (int j=0;j<32;j+=8){
                    float4 w0 = *(const float4*)(wr + j);
                    float4 w1 = *(const float4*)(wr + j + 4);
                    s0 += a[j+0]*w0.x + a[j+1]*w0.y + a[j+2]*w0.z + a[j+3]*w0.w;
                    s1 += a[j+4]*w1.x + a[j+5]*w1.y + a[j+6]*w1.z + a[j+7]*w1.w;
                }
                float s = s0 + s1;
                if (g==0) acc0 += s; else if (g==1) acc1 += s; else acc2 += s;
            }
        }
    }
    const int j = n0 + wp, b = lane;
    float pv0, pv1, pv2;
    if (pre){
        pv0 = pre[b*1536 + j];
        pv1 = pre[b*1536 + j + 512];
        pv2 = pre[b*1536 + j + 1024];
    } else {
        pv0 = b_ih[j]; pv1 = b_ih[j+512]; pv2 = b_ih[j+1024];
    }
    float ir = acc0 + pv0;
    float iz = acc1 + pv1;
    float in_ = acc2 + pv2;
    const int gg = b*1536 + j;
    float r = sigm(ir + gh[gg]);
    float z = sigm(iz + gh[gg+512]);
    float n = tanhf(in_ + r*gh[gg+1024]);
    float hv = (1.f - z)*n + z*hstate[b*512 + j];
    if (hpre) hpre[b*512 + j] = hv;
    hstate[b*512 + j] = fminf(fmaxf(hv, -10.f), 10.f);
    if (comb){
        comb[b*1024 + j]       = hv;
        comb[b*1024 + 512 + j] = clip100(ctxr[b*512 + j]);
    }
}

// attention core for (head h, batch group bg of 2), q precomputed
__device__ void attn_core(SmemU* smu, const Params& P, int h, int bg, float* ctxr){
    SmemA* sa = &smu->a;
    const int tid = threadIdx.x;
    if (tid < 128){
        int bi = tid >> 6, d = tid & 63;
        sa->qs2[bi][d] = P.q[(bg*2+bi)*512 + h*64 + d];
    }
    __syncthreads();

    for (int bi=0; bi<2; bi++){
        const int b = bg*2 + bi;
        const float* kp = P.Kh + ((size_t)(b*256 + tid))*512 + h*64;
        const float* qv = sa->qs2[bi];
        float s = 0.f;
        #pragma unroll
        for (int d=0; d<64; d+=4){
            float4 kv = *(const float4*)(kp + d);
            s += qv[d]*kv.x + qv[d+1]*kv.y + qv[d+2]*kv.z + qv[d+3]*kv.w;
        }
        s *= 0.125f;
        if (P.mask[b*256 + tid] == 0) s = -10000.f;
        float mx = block_max(s, sa->red);
        float e = expf(s - mx);
        sa->sc[tid] = e;
        float inv = 1.f / block_sum(e, sa->red);
        __syncthreads();
        {
            // V accumulation: 16 independent accumulators (MLP=16)
            int d = tid & 63, part = tid >> 6;
            const float* vp = P.Vh + ((size_t)(b*256))*512 + h*64 + d;
            float p[16];
            #pragma unroll
            for (int i=0;i<16;i++) p[i]=0.f;
            #pragma unroll
            for (int o=0;o<4;o++){
                int s2 = part*64 + o*16;
                #pragma unroll
                for (int i=0;i<16;i++)
                    p[i] += sa->sc[s2+i] * vp[(size_t)(s2+i)*512];
            }
            float r0 = ((p[0]+p[1])+(p[2]+p[3])) + ((p[4]+p[5])+(p[6]+p[7]));
            float r1 = ((p[8]+p[9])+(p[10]+p[11])) + ((p[12]+p[13])+(p[14]+p[15]));
            sa->psum[part][d] = r0 + r1;
        }
        __syncthreads();
        if (tid < 64)
            sa->ctxv[bi][tid] = (sa->psum[0][tid]+sa->psum[1][tid]
                               + sa->psum[2][tid]+sa->psum[3][tid]) * inv;
        __syncthreads();
    }
    // wo partials for 2 batches
    #pragma unroll
    for (int rr=0; rr<2; rr++){
        int n = tid + rr*256;
        const float4* wr = (const float4*)(P.wo + (size_t)n*512 + h*64);
        float s0=0.f, s1=0.f;
        #pragma unroll
        for (int j=0;j<16;j++){
            float4 w = wr[j];
            const float* c0 = &sa->ctxv[0][j*4];
            const float* c1 = &sa->ctxv[1][j*4];
            s0 += c0[0]*w.x + c0[1]*w.y + c0[2]*w.z + c0[3]*w.w;
            s1 += c1[0]*w.x + c1[1]*w.y + c1[2]*w.z + c1[3]*w.w;
        }
        atomicAdd(ctxr + (bg*2+0)*512 + n, s0);
        atomicAdd(ctxr + (bg*2+1)*512 + n, s1);
    }
}

#define PHASE(nt_, ...)                                               \
    for (int ti = (int)blockIdx.x; ti < (nt_); ti += NBLK2){          \
        __syncthreads();                                              \
        __VA_ARGS__                                                   \
    }                                                                 \
    bar++; grid_bar(bar);

__global__ void __launch_bounds__(256, 2) decoder_loop_kernel(Params P){
    __shared__ SmemU sm;
    const int tid = threadIdx.x;
    unsigned bar = 0;

    for (int t = 0; t < STEPS; t++){
        float* ctxc = P.ctxr + (t & 1)*Bb*Hh;

        // P1: qproj x32 + gh1 x64 + gh0 x64 + ctx-init x8  (168 tasks)
        PHASE(168, {
            if (ti < 32){
                gemm_task<2>(&sm, ti*16, P.h1, 512, P.wq, P.bq, P.q, 512, 1);
            } else if (ti < 96){
                gemm_task<3>(&sm, (ti-32)*24, P.h1, 512, P.w_hh1, P.b_hh1, P.gh1, 1536, 0);
            } else if (ti < 160){
                gemm_task<3>(&sm, (ti-96)*24, P.h0, 512, P.w_hh0, P.b_hh0, P.gh0, 1536, 0);
            } else {
                int base = (ti-160)*2048 + tid;
                #pragma unroll
                for (int e=0;e<8;e++){
                    int idx = base + e*256;
                    ctxc[idx] = P.bo[idx & 511];
                }
            }
        })
        // P2: attention only, fine-grained (h, bg2) x128 tasks
        PHASE(128, {
            attn_core(&sm, P, ti >> 4, ti & 15, ctxc);
        })
        // P3: gi0(ctx half, K=512) + GRU0 fused  (64 tasks)
        PHASE(64, {
            gru_task<true>(&sm, ti*8, ctxc, P.w_ih0, 1024, 512,
                           P.gi0e + (size_t)t*Bb*3*Hh, nullptr,
                           P.gh0, P.h0, P.h0p, nullptr, nullptr);
        })
        // P4: gi1(K=512) + GRU1 fused + comb store  (64 tasks)
        PHASE(64, {
            gru_task<false>(&sm, ti*8, P.h0p, P.w_ih1, 512, 0,
                            nullptr, P.b_ih1,
                            P.gh1, P.h1, nullptr,
                            P.comb + (size_t)t*Bb*2*Hh, ctxc);
        })
    }
}

// ---------------- driver -------------------------------------------------------
extern "C" void kernel_launch(void* const* d_in, const int* in_sizes, int n_in,
                              void* d_out, int out_size){
    const int*   tgt   = (const int*)  d_in[0];
    const float* enc   = (const float*)d_in[1];
    const float* dec   = (const float*)d_in[2];
    const int*   mask  = (const int*)  d_in[3];
    const float* embt  = (const float*)d_in[4];
    const float* w_ep  = (const float*)d_in[5];
    const float* b_ep  = (const float*)d_in[6];
    const float* wq    = (const float*)d_in[7];
    const float* bq    = (const float*)d_in[8];
    const float* wk    = (const float*)d_in[9];
    const float* bk    = (const float*)d_in[10];
    const float* wv    = (const float*)d_in[11];
    const float* bv    = (const float*)d_in[12];
    const float* wo    = (const float*)d_in[13];
    const float* bo    = (const float*)d_in[14];
    const float* w_ih0 = (const float*)d_in[15];
    const float* w_hh0 = (const float*)d_in[16];
    const float* b_ih0 = (const float*)d_in[17];
    const float* b_hh0 = (const float*)d_in[18];
    const float* w_ih1 = (const float*)d_in[19];
    const float* w_hh1 = (const float*)d_in[20];
    const float* b_ih1 = (const float*)d_in[21];
    const float* b_hh1 = (const float*)d_in[22];
    const float* w_o1  = (const float*)d_in[23];
    const float* b_o1  = (const float*)d_in[24];
    const float* w_o2  = (const float*)d_in[25];
    const float* b_o2  = (const float*)d_in[26];
    float* out = (float*)d_out;

    float* buf = nullptr;
    cudaGetSymbolAddress((void**)&buf, g_buf);
    __nv_bfloat16 *whi, *wlo, *ahi, *alo;
    cudaGetSymbolAddress((void**)&whi, g_whi);
    cudaGetSymbolAddress((void**)&wlo, g_wlo);
    cudaGetSymbolAddress((void**)&ahi, g_ahi);
    cudaGetSymbolAddress((void**)&alo, g_alo);

    Params P;
    P.mask = mask;
    P.wq = wq; P.bq = bq; P.wo = wo; P.bo = bo;
    P.w_ih0 = w_ih0; P.w_hh0 = w_hh0; P.b_ih0 = b_ih0; P.b_hh0 = b_hh0;
    P.w_ih1 = w_ih1; P.w_hh1 = w_hh1; P.b_ih1 = b_ih1; P.b_hh1 = b_hh1;
    P.Kh = buf + O_KH; P.Vh = buf + O_VH;
    P.h0 = buf + O_H0; P.h1 = buf + O_H1; P.h0p = buf + O_H0P;
    P.q = buf + O_Q; P.ctxr = buf + O_CTXR;
    P.gh0 = buf + O_GH0; P.gh1 = buf + O_GH1;
    P.gi0e = buf + O_GI0E;
    P.comb = buf + O_COMB;
    float* Eg = buf + O_EG;
    float* emba = buf + O_EMBA;
    float* o1 = buf + O_O1;

    reset_kernel<<<1, 32>>>();
    init_kernel<<<(Bb*Hh+255)/256, 256>>>(dec, bo, P.h0, P.h1, P.ctxr);
    zero_kernel<<<(Bb*Vv+255)/256, 256>>>(out);

    // one-time: split w_o2 into bf16 hi/lo
    conv_split_kernel<<<(Vv*Hh+255)/256, 256>>>(w_o2, whi, wlo, Vv*Hh);

    // hoisted: embedding gather + projection for all 63 steps
    gather_emb_kernel<<<(STEPS*Bb*Ee)/256, 256>>>(tgt, embt, Eg);
    gemm128_kernel<<<dim3(Hh/128, (STEPS*Bb+127)/128), 256>>>(
        Eg, w_ep, b_ep, emba, STEPS*Bb, Hh, Ee, Ee, 0);
    // hoisted: emb half of gi0 for all steps
    gemm128_kernel<<<dim3((3*Hh)/128, (STEPS*Bb+127)/128), 256>>>(
        emba, w_ih0, b_ih0, (float*)P.gi0e, STEPS*Bb, 3*Hh, Hh, 2*Hh, 0);

    // step-invariant K/V projections (Kh clipped, Vh plain)
    gemm128_kernel<<<dim3(Hh/128, (Bb*Ss)/128), 256>>>(enc, wk, bk, (float*)P.Kh, Bb*Ss, Hh, Hh, Hh, 1);
    gemm128_kernel<<<dim3(Hh/128, (Bb*Ss)/128), 256>>>(enc, wv, bv, (float*)P.Vh, Bb*Ss, Hh, Hh, Hh, 0);

    // full 63-step recurrence, 4 flat grid barriers per step
    decoder_loop_kernel<<<NBLK2, 256>>>(P);

    // batched output MLP: o1 = relu(comb @ w_o1^T + b_o1)  (fp32)
    gemm128_kernel<<<dim3(Hh/128, (STEPS*Bb+127)/128), 256>>>(
        P.comb, w_o1, b_o1, o1, STEPS*Bb, Hh, 2*Hh, 2*Hh, 2);
    // split o1 into bf16 hi/lo, then tensor-core vocab GEMM (128x128 tiles)
    conv_split_kernel<<<(STEPS*Bb*Hh+255)/256, 256>>>(o1, ahi, alo, STEPS*Bb*Hh);
    cudaFuncSetAttribute(gemm_mma_vocab, cudaFuncAttributeMaxDynamicSharedMemorySize, VOCAB_SMEM);
    gemm_mma_vocab<<<dim3(Vv/128, 16), 256, VOCAB_SMEM>>>(ahi, alo, whi, wlo, b_o2, out);
}

// round 16
// speedup vs baseline: 1.3485x; 1.0128x over previous
#include <cuda_runtime.h>
#include <cuda_bf16.h>
#include <math.h>

#define Bb 32
#define Tt 64
#define Ss 256
#define Hh 512
#define Ee 256
#define Vv 32000
#define NHh 8
#define STEPS 63
#define NBLK2 296

// ---------------- scratch ----------------------------------------------------
#define O_KH   0
#define O_VH   (O_KH  + Bb*Ss*Hh)
#define O_H0   (O_VH  + Bb*Ss*Hh)
#define O_H1   (O_H0  + Bb*Hh)
#define O_H0P  (O_H1  + Bb*Hh)
#define O_Q    (O_H0P + Bb*Hh)
#define O_CTXR (O_Q   + Bb*Hh)
#define O_GH0  (O_CTXR+ 2*Bb*Hh)
#define O_GH1  (O_GH0 + Bb*3*Hh)
#define O_EG   (O_GH1 + Bb*3*Hh)
#define O_EMBA (O_EG  + STEPS*Bb*Ee)
#define O_GI0E (O_EMBA+ STEPS*Bb*Hh)
#define O_COMB (O_GI0E+ STEPS*Bb*3*Hh)
#define O_O1   (O_COMB+ STEPS*Bb*2*Hh)
#define O_TOTAL (O_O1 + STEPS*Bb*Hh)

__device__ float g_buf[O_TOTAL];
__device__ unsigned g_cnt_arr[64];
__device__ unsigned g_gen_arr[64];
__device__ __nv_bfloat16 g_whi[Vv*Hh];
__device__ __nv_bfloat16 g_wlo[Vv*Hh];
__device__ __nv_bfloat16 g_ahi[STEPS*Bb*Hh];
__device__ __nv_bfloat16 g_alo[STEPS*Bb*Hh];

__device__ __forceinline__ float clip100(float v){ return fminf(fmaxf(v,-100.f),100.f); }
__device__ __forceinline__ float sigm(float x){ return 1.f/(1.f+expf(-x)); }

// ---------------- setup kernels ----------------------------------------------
__global__ void init_kernel(const float* __restrict__ dec, const float* __restrict__ bo,
                            float* h0, float* h1, float* ctxr0){
    int i = blockIdx.x*256 + threadIdx.x;
    if (i < Bb*Hh){
        float v = fminf(fmaxf(dec[i], -10.f), 10.f);
        h0[i] = v; h1[i] = v;
        ctxr0[i] = bo[i & 511];
    }
}

__global__ void reset_kernel(){
    if (threadIdx.x == 0 && blockIdx.x == 0){ g_cnt_arr[0] = 0u; g_gen_arr[0] = 0u; }
}

__global__ void zero_kernel(float* __restrict__ out){
    int i = blockIdx.x*256 + threadIdx.x;
    if (i < Bb*Vv){
        int b = i / Vv, v = i % Vv;
        out[(size_t)b*Tt*Vv + v] = 0.f;
    }
}

__global__ void gather_emb_kernel(const int* __restrict__ tgt,
                                  const float* __restrict__ embt, float* __restrict__ Eg){
    int idx = blockIdx.x*256 + threadIdx.x;
    int row = idx >> 8, e = idx & 255;
    int t = row >> 5, b = row & 31;
    int tok = tgt[b*Tt + t];
    Eg[row*Ee + e] = embt[tok*Ee + e];
}

// fp32 -> bf16 hi/lo split
__global__ void conv_split_kernel(const float* __restrict__ src,
                                  __nv_bfloat16* __restrict__ hi,
                                  __nv_bfloat16* __restrict__ lo, int n){
    int i = blockIdx.x*256 + threadIdx.x;
    if (i < n){
        float v = src[i];
        __nv_bfloat16 h = __float2bfloat16(v);
        hi[i] = h;
        lo[i] = __float2bfloat16(v - __bfloat162float(h));
    }
}

// ---------------- big tiled SGEMM, double-buffered ----------------------------
// mode: 0 plain, 1 clip100, 2 relu;  ldw = row stride of W (>= K)
__global__ void gemm128_kernel(const float* __restrict__ A, const float* __restrict__ W,
                               const float* __restrict__ bias, float* __restrict__ C,
                               int M, int N, int K, int ldw, int mode){
    __shared__ float As[2][8][128];
    __shared__ float Ws[2][8][128];
    const int tid = threadIdx.x;
    const int bm = blockIdx.y * 128;
    const int bn = blockIdx.x * 128;
    const int lrow = tid >> 1;
    const int lk4  = (tid & 1) * 4;
    const int tx = tid & 15, ty = tid >> 4;

    float acc[8][8];
    #pragma unroll
    for (int i=0;i<8;i++)
        #pragma unroll
        for (int j=0;j<8;j++) acc[i][j]=0.f;

    float4 av, wv;
    auto ld = [&](int kb){
        av = make_float4(0.f,0.f,0.f,0.f);
        int ar = bm + lrow;
        if (ar < M) av = *(const float4*)(A + (size_t)ar*K + kb + lk4);
        wv = *(const float4*)(W + (size_t)(bn+lrow)*ldw + kb + lk4);
    };
    auto st = [&](int p){
        As[p][lk4+0][lrow]=av.x; As[p][lk4+1][lrow]=av.y;
        As[p][lk4+2][lrow]=av.z; As[p][lk4+3][lrow]=av.w;
        Ws[p][lk4+0][lrow]=wv.x; Ws[p][lk4+1][lrow]=wv.y;
        Ws[p][lk4+2][lrow]=wv.z; Ws[p][lk4+3][lrow]=wv.w;
    };

    ld(0); st(0);
    __syncthreads();
    int p = 0;
    for (int kb = 0; kb < K; kb += 8){
        if (kb + 8 < K) ld(kb + 8);
        #pragma unroll
        for (int k=0;k<8;k++){
            float4 a0 = *(const float4*)&As[p][k][ty*4];
            float4 a1 = *(const float4*)&As[p][k][64 + ty*4];
            float4 b0 = *(const float4*)&Ws[p][k][tx*4];
            float4 b1 = *(const float4*)&Ws[p][k][64 + tx*4];
            float am[8] = {a0.x,a0.y,a0.z,a0.w, a1.x,a1.y,a1.z,a1.w};
            float bm_[8]= {b0.x,b0.y,b0.z,b0.w, b1.x,b1.y,b1.z,b1.w};
            #pragma unroll
            for (int i=0;i<8;i++)
                #pragma unroll
                for (int j=0;j<8;j++)
                    acc[i][j] += am[i]*bm_[j];
        }
        if (kb + 8 < K) st(p ^ 1);
        __syncthreads();
        p ^= 1;
    }

    #pragma unroll
    for (int i=0;i<8;i++){
        int gm = bm + (i<4 ? ty*4+i : 64 + ty*4 + (i-4));
        if (gm >= M) continue;
        #pragma unroll
        for (int j=0;j<8;j++){
            int gn = bn + (j<4 ? tx*4+j : 64 + tx*4 + (j-4));
            float v = acc[i][j] + bias[gn];
            if (mode==1)      v = clip100(v);
            else if (mode==2) v = fmaxf(v, 0.f);
            C[(size_t)gm*N + gn] = v;
        }
    }
}

// ---------------- split-bf16 tensor-core vocab GEMM (128x128, cp.async) --------
#define MMA_BF16(cc, aa, bb) \
    asm volatile("mma.sync.aligned.m16n8k16.row.col.f32.bf16.bf16.f32 " \
        "{%0,%1,%2,%3},{%4,%5,%6,%7},{%8,%9},{%0,%1,%2,%3};" \
        : "+f"(cc[0]),"+f"(cc[1]),"+f"(cc[2]),"+f"(cc[3]) \
        : "r"(aa[0]),"r"(aa[1]),"r"(aa[2]),"r"(aa[3]), "r"(bb[0]),"r"(bb[1]))

#define VOCAB_SMEM (4*5120*2 + 4*5120*2)

__global__ void __launch_bounds__(256, 2) gemm_mma_vocab(
    const __nv_bfloat16* __restrict__ Ahi, const __nv_bfloat16* __restrict__ Alo,
    const __nv_bfloat16* __restrict__ Whi, const __nv_bfloat16* __restrict__ Wlo,
    const float* __restrict__ bias, float* __restrict__ out)
{
    extern __shared__ __nv_bfloat16 dsm[];
    const unsigned smem_u32 = (unsigned)__cvta_generic_to_shared(dsm);
    const int tid = threadIdx.x;
    const int lane = tid & 31, wid = tid >> 5;
    const int wm = wid & 1, wn = wid >> 1;
    const int g = lane >> 2, tg = lane & 3;
    const int bn = blockIdx.x * 128;
    const int bm = blockIdx.y * 128;

    float c[16][4];
    #pragma unroll
    for (int i=0;i<16;i++){ c[i][0]=0.f; c[i][1]=0.f; c[i][2]=0.f; c[i][3]=0.f; }

    const int row  = tid >> 1;
    const int h16  = (tid & 1) * 16;
    const int apred = ((bm + row) < STEPS*Bb) ? 16 : 0;

    auto cp16 = [&](unsigned dst, const void* src, int sz){
        asm volatile("cp.async.cg.shared.global [%0], [%1], 16, %2;"
                     :: "r"(dst), "l"(src), "r"(sz) : "memory");
    };
    auto cp_chunk = [&](int kb, int st){
        const size_t aoff = (size_t)(bm + row)*512 + kb + h16;
        unsigned da = smem_u32 + ((st*2+0)*5120 + row*40 + h16)*2;
        cp16(da,      Ahi + aoff,     apred);
        cp16(da + 16, Ahi + aoff + 8, apred);
        unsigned dal = da + 5120*2;
        cp16(dal,      Alo + aoff,     apred);
        cp16(dal + 16, Alo + aoff + 8, apred);
        const size_t woff = (size_t)(bn + row)*512 + kb + h16;
        unsigned dw = smem_u32 + (20480 + (st*2+0)*5120 + row*40 + h16)*2;
        cp16(dw,      Whi + woff,     16);
        cp16(dw + 16, Whi + woff + 8, 16);
        unsigned dwl = dw + 5120*2;
        cp16(dwl,      Wlo + woff,     16);
        cp16(dwl + 16, Wlo + woff + 8, 16);
        asm volatile("cp.async.commit_group;");
    };

    cp_chunk(0, 0);
    int st = 0;
    for (int kb = 0; kb < 512; kb += 32){
        if (kb + 32 < 512){
            cp_chunk(kb + 32, st ^ 1);
            asm volatile("cp.async.wait_group 1;");
        } else {
            asm volatile("cp.async.wait_group 0;");
        }
        __syncthreads();
        const __nv_bfloat16* A0 = dsm + (st*2+0)*5120;
        const __nv_bfloat16* A1 = dsm + (st*2+1)*5120;
        const __nv_bfloat16* W0 = dsm + 20480 + (st*2+0)*5120;
        const __nv_bfloat16* W1 = dsm + 20480 + (st*2+1)*5120;
        #pragma unroll
        for (int ko = 0; ko < 32; ko += 16){
            unsigned ah[4][4], al[4][4], bh[4][2], bl[4][2];
            const int c0 = ko + 2*tg, c8 = c0 + 8;
            #pragma unroll
            for (int mt=0; mt<4; mt++){
                int r0 = (wm*64 + mt*16 + g)*40;
                ah[mt][0] = *(const unsigned*)&A0[r0 + c0];
                ah[mt][1] = *(const unsigned*)&A0[r0 + 320 + c0];
                ah[mt][2] = *(const unsigned*)&A0[r0 + c8];
                ah[mt][3] = *(const unsigned*)&A0[r0 + 320 + c8];
                al[mt][0] = *(const unsigned*)&A1[r0 + c0];
                al[mt][1] = *(const unsigned*)&A1[r0 + 320 + c0];
                al[mt][2] = *(const unsigned*)&A1[r0 + c8];
                al[mt][3] = *(const unsigned*)&A1[r0 + 320 + c8];
            }
            #pragma unroll
            for (int nt=0; nt<4; nt++){
                int n0 = (wn*32 + nt*8 + g)*40;
                bh[nt][0] = *(const unsigned*)&W0[n0 + c0];
                bh[nt][1] = *(const unsigned*)&W0[n0 + c8];
                bl[nt][0] = *(const unsigned*)&W1[n0 + c0];
                bl[nt][1] = *(const unsigned*)&W1[n0 + c8];
            }
            #pragma unroll
            for (int mt=0; mt<4; mt++)
                #pragma unroll
                for (int nt=0; nt<4; nt++){
                    MMA_BF16(c[mt*4+nt], ah[mt], bh[nt]);
                    MMA_BF16(c[mt*4+nt], ah[mt], bl[nt]);
                    MMA_BF16(c[mt*4+nt], al[mt], bh[nt]);
                }
        }
        __syncthreads();
        st ^= 1;
    }
    #pragma unroll
    for (int nt=0; nt<4; nt++){
        int col = bn + wn*32 + nt*8 + 2*tg;
        float b0 = bias[col], b1 = bias[col+1];
        #pragma unroll
        for (int mt=0; mt<4; mt++){
            #pragma unroll
            for (int half=0; half<2; half++){
                int gm = bm + wm*64 + mt*16 + g + half*8;
                if (gm >= STEPS*Bb) continue;
                int bb2 = gm & 31, tt2 = gm >> 5;
                float v0 = clip100(c[mt*4+nt][half*2+0] + b0);
                float v1 = clip100(c[mt*4+nt][half*2+1] + b1);
                *(float2*)&out[((size_t)bb2*Tt + tt2 + 1)*Vv + col] = make_float2(v0, v1);
            }
        }
    }
}

// ---------------- persistent decoder loop -------------------------------------
struct SmemG { float As[32*132]; float Ws[32*128]; };
struct SmemA { float qs[64]; float sc[256]; float red[64];
               float psum[4][64]; float ctxv[64]; };
union SmemU { SmemG g; SmemA a; };

struct Params {
    const int* mask;
    const float* wq;   const float* bq;
    const float* wo;   const float* bo;
    const float* w_ih0; const float* w_hh0; const float* b_ih0; const float* b_hh0;
    const float* w_ih1; const float* w_hh1; const float* b_ih1; const float* b_hh1;
    const float* Kh; const float* Vh; const float* gi0e;
    float *h0, *h1, *h0p, *q, *ctxr, *gh0, *gh1, *comb;
};

// flat counter barrier (best measured)
__device__ __forceinline__ void grid_bar(unsigned target){
    __syncthreads();
    if (threadIdx.x == 0){
        __threadfence();
        unsigned prev = atomicAdd(&g_cnt_arr[0], 1u);
        if (prev == target*NBLK2 - 1u){
            __threadfence();
            asm volatile("st.release.gpu.u32 [%0], %1;" :: "l"(&g_gen_arr[0]), "r"(target) : "memory");
        } else {
            unsigned v;
            do {
                asm volatile("ld.acquire.gpu.u32 %0, [%1];" : "=r"(v) : "l"(&g_gen_arr[0]) : "memory");
            } while (v < target);
        }
    }
    __syncthreads();
}

__device__ __forceinline__ float block_max(float v, float* red){
    #pragma unroll
    for (int off=16; off>0; off>>=1) v = fmaxf(v, __shfl_xor_sync(0xffffffffu, v, off));
    if ((threadIdx.x & 31) == 0) red[threadIdx.x >> 5] = v;
    __syncthreads();
    if (threadIdx.x < 8){
        float x = red[threadIdx.x];
        #pragma unroll
        for (int off=4; off>0; off>>=1) x = fmaxf(x, __shfl_xor_sync(0xffu, x, off));
        if (threadIdx.x == 0) red[0] = x;
    }
    __syncthreads();
    float r = red[0];
    __syncthreads();
    return r;
}
__device__ __forceinline__ float block_sum(float v, float* red){
    #pragma unroll
    for (int off=16; off>0; off>>=1) v += __shfl_xor_sync(0xffffffffu, v, off);
    if ((threadIdx.x & 31) == 0) red[threadIdx.x >> 5] = v;
    __syncthreads();
    if (threadIdx.x < 8){
        float x = red[threadIdx.x];
        #pragma unroll
        for (int off=4; off>0; off>>=1) x += __shfl_xor_sync(0xffu, x, off);
        if (threadIdx.x == 0) red[0] = x;
    }
    __syncthreads();
    float r = red[0];
    __syncthreads();
    return r;
}

template<int NW>
__device__ void gemm_task(SmemU* sm, int n0, const float* __restrict__ A,
                          int K, const float* __restrict__ W, const float* __restrict__ bias,
                          float* __restrict__ C, int ldc, int act)
{
    const int tid = threadIdx.x;
    const int lane = tid & 31;
    const int wp = tid >> 5;
    float acc[NW];
    #pragma unroll
    for (int i=0;i<NW;i++) acc[i]=0.f;

    float4 pa[4];
    float4 pw[NW];
    auto loadA = [&](int kb){
        #pragma unroll
        for (int p2=0;p2<4;p2++){
            int idx = tid + p2*256;
            int r = idx >> 5, c4 = (idx & 31)*4;
            pa[p2] = *(const float4*)(A + r*512 + kb + c4);
        }
    };
    auto loadW = [&](int kb){
        #pragma unroll
        for (int q2=0;q2<NW;q2++){
            int idx = tid + q2*256;
            int n = idx >> 5, c4 = (idx & 31)*4;
            pw[q2] = *(const float4*)(W + (size_t)(n0+n)*K + kb + c4);
        }
    };

    loadA(0); loadW(0);
    for (int kb=0; kb<K; kb+=128){
        __syncthreads();
        #pragma unroll
        for (int p2=0;p2<4;p2++){
            int idx = tid + p2*256;
            int r = idx >> 5, c4 = (idx & 31)*4;
            *(float4*)&sm->g.As[r*132 + c4] = pa[p2];
        }
        #pragma unroll
        for (int q2=0;q2<NW;q2++){
            int idx = tid + q2*256;
            int n = idx >> 5, c4 = (idx & 31)*4;
            *(float4*)&sm->g.Ws[n*128 + c4] = pw[q2];
        }
        __syncthreads();
        if (kb + 128 < K){ loadA(kb+128); loadW(kb+128); }
        #pragma unroll
        for (int kc=0; kc<128; kc+=32){
            float a[32];
            #pragma unroll
            for (int j=0;j<32;j+=4)
                *(float4*)&a[j] = *(const float4*)&sm->g.As[lane*132 + kc + j];
            #pragma unroll
            for (int nn=0;nn<NW;nn++){
                const float* wr = &sm->g.Ws[(wp*NW+nn)*128 + kc];
                float s0=0.f, s1=0.f;
                #pragma unroll
                for (int j=0;j<32;j+=8){
                    float4 w0 = *(const float4*)(wr + j);
                    float4 w1 = *(const float4*)(wr + j + 4);
                    s0 += a[j+0]*w0.x + a[j+1]*w0.y + a[j+2]*w0.z + a[j+3]*w0.w;
                    s1 += a[j+4]*w1.x + a[j+5]*w1.y + a[j+6]*w1.z + a[j+7]*w1.w;
                }
                acc[nn] += s0 + s1;
            }
        }
    }
    #pragma unroll
    for (int nn=0;nn<NW;nn++){
        int n = n0 + wp*NW + nn;
        float v = acc[nn] + bias[n];
        if (act) v = clip100(v);
        C[lane*ldc + n] = v;
    }
}

// fused GEMM-triplet (K=512) + GRU nonlinearity.
template<bool CLIPA>
__device__ void gru_task(SmemU* sm, int n0, const float* __restrict__ A,
                         const float* __restrict__ W, int wstride, int woff,
                         const float* __restrict__ pre, const float* __restrict__ b_ih,
                         const float* __restrict__ gh,
                         float* __restrict__ hstate, float* __restrict__ hpre,
                         float* __restrict__ comb, const float* __restrict__ ctxr)
{
    const int tid = threadIdx.x;
    const int lane = tid & 31;
    const int wp = tid >> 5;
    float acc0=0.f, acc1=0.f, acc2=0.f;

    float4 pa[4];
    float4 pw[3];
    auto loadA = [&](int kb){
        #pragma unroll
        for (int p2=0;p2<4;p2++){
            int idx = tid + p2*256;
            int r = idx >> 5, c4 = (idx & 31)*4;
            float4 v = *(const float4*)(A + r*512 + kb + c4);
            if (CLIPA){
                v.x=clip100(v.x); v.y=clip100(v.y); v.z=clip100(v.z); v.w=clip100(v.w);
            }
            pa[p2] = v;
        }
    };
    auto loadW = [&](int kb){
        #pragma unroll
        for (int q2=0;q2<3;q2++){
            int idx = tid + q2*256;
            int nn = idx >> 5, c4 = (idx & 31)*4;
            int w = nn / 3, g = nn % 3;
            int grow = n0 + w + g*512;
            pw[q2] = *(const float4*)(W + (size_t)grow*wstride + woff + kb + c4);
        }
    };

    loadA(0); loadW(0);
    #pragma unroll
    for (int kb=0; kb<512; kb+=128){
        __syncthreads();
        #pragma unroll
        for (int p2=0;p2<4;p2++){
            int idx = tid + p2*256;
            int r = idx >> 5, c4 = (idx & 31)*4;
            *(float4*)&sm->g.As[r*132 + c4] = pa[p2];
        }
        #pragma unroll
        for (int q2=0;q2<3;q2++){
            int idx = tid + q2*256;
            int nn = idx >> 5, c4 = (idx & 31)*4;
            int w = nn / 3, g = nn % 3;
            *(float4*)&sm->g.Ws[(w*3+g)*128 + c4] = pw[q2];
        }
        __syncthreads();
        if (kb + 128 < 512){ loadA(kb+128); loadW(kb+128); }
        #pragma unroll
        for (int kc=0; kc<128; kc+=32){
            float a[32];
            #pragma unroll
            for (int j=0;j<32;j+=4)
                *(float4*)&a[j] = *(const float4*)&sm->g.As[lane*132 + kc + j];
            #pragma unroll
            for (int g=0; g<3; g++){
                const float* wr = &sm->g.Ws[(wp*3+g)*128 + kc];
                float s0=0.f, s1=0.f;
                #pragma unroll
                for (int j=0;j<32;j+=8){
                    float4 w0 = *(const float4*)(wr + j);
                    float4 w1 = *(const float4*)(wr + j + 4);
                    s0 += a[j+0]*w0.x + a[j+1]*w0.y + a[j+2]*w0.z + a[j+3]*w0.w;
                    s1 += a[j+4]*w1.x + a[j+5]*w1.y + a[j+6]*w1.z + a[j+7]*w1.w;
                }
                float s = s0 + s1;
                if (g==0) acc0 += s; else if (g==1) acc1 += s; else acc2 += s;
            }
        }
    }
    const int j = n0 + wp, b = lane;
    float pv0, pv1, pv2;
    if (pre){
        pv0 = pre[b*1536 + j];
        pv1 = pre[b*1536 + j + 512];
        pv2 = pre[b*1536 + j + 1024];
    } else {
        pv0 = b_ih[j]; pv1 = b_ih[j+512]; pv2 = b_ih[j+1024];
    }
    float ir = acc0 + pv0;
    float iz = acc1 + pv1;
    float in_ = acc2 + pv2;
    const int gg = b*1536 + j;
    float r = sigm(ir + gh[gg]);
    float z = sigm(iz + gh[gg+512]);
    float n = tanhf(in_ + r*gh[gg+1024]);
    float hv = (1.f - z)*n + z*hstate[b*512 + j];
    if (hpre) hpre[b*512 + j] = hv;
    hstate[b*512 + j] = fminf(fmaxf(hv, -10.f), 10.f);
    if (comb){
        comb[b*1024 + j]       = hv;
        comb[b*1024 + 512 + j] = clip100(ctxr[b*512 + j]);
    }
}

// attention core for (head h, single batch b), q precomputed
__device__ void attn_core(SmemU* smu, const Params& P, int h, int b, float* ctxr){
    SmemA* sa = &smu->a;
    const int tid = threadIdx.x;
    if (tid < 64) sa->qs[tid] = P.q[b*512 + h*64 + tid];
    __syncthreads();

    const float* kp = P.Kh + ((size_t)(b*256 + tid))*512 + h*64;
    float s = 0.f;
    #pragma unroll
    for (int d=0; d<64; d+=4){
        float4 kv = *(const float4*)(kp + d);
        s += sa->qs[d]*kv.x + sa->qs[d+1]*kv.y + sa->qs[d+2]*kv.z + sa->qs[d+3]*kv.w;
    }
    s *= 0.125f;
    if (P.mask[b*256 + tid] == 0) s = -10000.f;
    float mx = block_max(s, sa->red);
    float e = expf(s - mx);
    sa->sc[tid] = e;
    float inv = 1.f / block_sum(e, sa->red);
    __syncthreads();
    {
        // V accumulation: 16 independent accumulators (MLP=16)
        int d = tid & 63, part = tid >> 6;
        const float* vp = P.Vh + ((size_t)(b*256))*512 + h*64 + d;
        float p[16];
        #pragma unroll
        for (int i=0;i<16;i++) p[i]=0.f;
        #pragma unroll
        for (int o=0;o<4;o++){
            int s2 = part*64 + o*16;
            #pragma unroll
            for (int i=0;i<16;i++)
                p[i] += sa->sc[s2+i] * vp[(size_t)(s2+i)*512];
        }
        float r0 = ((p[0]+p[1])+(p[2]+p[3])) + ((p[4]+p[5])+(p[6]+p[7]));
        float r1 = ((p[8]+p[9])+(p[10]+p[11])) + ((p[12]+p[13])+(p[14]+p[15]));
        sa->psum[part][d] = r0 + r1;
    }
    __syncthreads();
    if (tid < 64)
        sa->ctxv[tid] = (sa->psum[0][tid]+sa->psum[1][tid]
                       + sa->psum[2][tid]+sa->psum[3][tid]) * inv;
    __syncthreads();
    // wo partial for this (h, b)
    #pragma unroll
    for (int rr=0; rr<2; rr++){
        int n = tid + rr*256;
        const float4* wr = (const float4*)(P.wo + (size_t)n*512 + h*64);
        float s0=0.f;
        #pragma unroll
        for (int j=0;j<16;j++){
            float4 w = wr[j];
            const float* c0 = &sa->ctxv[j*4];
            s0 += c0[0]*w.x + c0[1]*w.y + c0[2]*w.z + c0[3]*w.w;
        }
        atomicAdd(ctxr + b*512 + n, s0);
    }
}

#define PHASE(nt_, ...)                                               \
    for (int ti = (int)blockIdx.x; ti < (nt_); ti += NBLK2){          \
        __syncthreads();                                              \
        __VA_ARGS__                                                   \
    }                                                                 \
    bar++; grid_bar(bar);

__global__ void __launch_bounds__(256, 2) decoder_loop_kernel(Params P){
    __shared__ SmemU sm;
    const int tid = threadIdx.x;
    unsigned bar = 0;

    for (int t = 0; t < STEPS; t++){
        float* ctxc = P.ctxr + (t & 1)*Bb*Hh;

        // P1: qproj x32 + gh1 x96 + gh0 x96 + ctx-init x8  (232 tasks)
        PHASE(232, {
            if (ti < 32){
                gemm_task<2>(&sm, ti*16, P.h1, 512, P.wq, P.bq, P.q, 512, 1);
            } else if (ti < 128){
                gemm_task<2>(&sm, (ti-32)*16, P.h1, 512, P.w_hh1, P.b_hh1, P.gh1, 1536, 0);
            } else if (ti < 224){
                gemm_task<2>(&sm, (ti-128)*16, P.h0, 512, P.w_hh0, P.b_hh0, P.gh0, 1536, 0);
            } else {
                int base = (ti-224)*2048 + tid;
                #pragma unroll
                for (int e=0;e<8;e++){
                    int idx = base + e*256;
                    ctxc[idx] = P.bo[idx & 511];
                }
            }
        })
        // P2: attention only, (h, b) x256 tasks
        PHASE(256, {
            attn_core(&sm, P, ti >> 5, ti & 31, ctxc);
        })
        // P3: gi0(ctx half, K=512) + GRU0 fused  (64 tasks)
        PHASE(64, {
            gru_task<true>(&sm, ti*8, ctxc, P.w_ih0, 1024, 512,
                           P.gi0e + (size_t)t*Bb*3*Hh, nullptr,
                           P.gh0, P.h0, P.h0p, nullptr, nullptr);
        })
        // P4: gi1(K=512) + GRU1 fused + comb store  (64 tasks)
        PHASE(64, {
            gru_task<false>(&sm, ti*8, P.h0p, P.w_ih1, 512, 0,
                            nullptr, P.b_ih1,
                            P.gh1, P.h1, nullptr,
                            P.comb + (size_t)t*Bb*2*Hh, ctxc);
        })
    }
}

// ---------------- driver -------------------------------------------------------
extern "C" void kernel_launch(void* const* d_in, const int* in_sizes, int n_in,
                              void* d_out, int out_size){
    const int*   tgt   = (const int*)  d_in[0];
    const float* enc   = (const float*)d_in[1];
    const float* dec   = (const float*)d_in[2];
    const int*   mask  = (const int*)  d_in[3];
    const float* embt  = (const float*)d_in[4];
    const float* w_ep  = (const float*)d_in[5];
    const float* b_ep  = (const float*)d_in[6];
    const float* wq    = (const float*)d_in[7];
    const float* bq    = (const float*)d_in[8];
    const float* wk    = (const float*)d_in[9];
    const float* bk    = (const float*)d_in[10];
    const float* wv    = (const float*)d_in[11];
    const float* bv    = (const float*)d_in[12];
    const float* wo    = (const float*)d_in[13];
    const float* bo    = (const float*)d_in[14];
    const float* w_ih0 = (const float*)d_in[15];
    const float* w_hh0 = (const float*)d_in[16];
    const float* b_ih0 = (const float*)d_in[17];
    const float* b_hh0 = (const float*)d_in[18];
    const float* w_ih1 = (const float*)d_in[19];
    const float* w_hh1 = (const float*)d_in[20];
    const float* b_ih1 = (const float*)d_in[21];
    const float* b_hh1 = (const float*)d_in[22];
    const float* w_o1  = (const float*)d_in[23];
    const float* b_o1  = (const float*)d_in[24];
    const float* w_o2  = (const float*)d_in[25];
    const float* b_o2  = (const float*)d_in[26];
    float* out = (float*)d_out;

    float* buf = nullptr;
    cudaGetSymbolAddress((void**)&buf, g_buf);
    __nv_bfloat16 *whi, *wlo, *ahi, *alo;
    cudaGetSymbolAddress((void**)&whi, g_whi);
    cudaGetSymbolAddress((void**)&wlo, g_wlo);
    cudaGetSymbolAddress((void**)&ahi, g_ahi);
    cudaGetSymbolAddress((void**)&alo, g_alo);

    Params P;
    P.mask = mask;
    P.wq = wq; P.bq = bq; P.wo = wo; P.bo = bo;
    P.w_ih0 = w_ih0; P.w_hh0 = w_hh0; P.b_ih0 = b_ih0; P.b_hh0 = b_hh0;
    P.w_ih1 = w_ih1; P.w_hh1 = w_hh1; P.b_ih1 = b_ih1; P.b_hh1 = b_hh1;
    P.Kh = buf + O_KH; P.Vh = buf + O_VH;
    P.h0 = buf + O_H0; P.h1 = buf + O_H1; P.h0p = buf + O_H0P;
    P.q = buf + O_Q; P.ctxr = buf + O_CTXR;
    P.gh0 = buf + O_GH0; P.gh1 = buf + O_GH1;
    P.gi0e = buf + O_GI0E;
    P.comb = buf + O_COMB;
    float* Eg = buf + O_EG;
    float* emba = buf + O_EMBA;
    float* o1 = buf + O_O1;

    reset_kernel<<<1, 32>>>();
    init_kernel<<<(Bb*Hh+255)/256, 256>>>(dec, bo, P.h0, P.h1, P.ctxr);
    zero_kernel<<<(Bb*Vv+255)/256, 256>>>(out);

    // one-time: split w_o2 into bf16 hi/lo
    conv_split_kernel<<<(Vv*Hh+255)/256, 256>>>(w_o2, whi, wlo, Vv*Hh);

    // hoisted: embedding gather + projection for all 63 steps
    gather_emb_kernel<<<(STEPS*Bb*Ee)/256, 256>>>(tgt, embt, Eg);
    gemm128_kernel<<<dim3(Hh/128, (STEPS*Bb+127)/128), 256>>>(
        Eg, w_ep, b_ep, emba, STEPS*Bb, Hh, Ee, Ee, 0);
    // hoisted: emb half of gi0 for all steps
    gemm128_kernel<<<dim3((3*Hh)/128, (STEPS*Bb+127)/128), 256>>>(
        emba, w_ih0, b_ih0, (float*)P.gi0e, STEPS*Bb, 3*Hh, Hh, 2*Hh, 0);

    // step-invariant K/V projections (Kh clipped, Vh plain)
    gemm128_kernel<<<dim3(Hh/128, (Bb*Ss)/128), 256>>>(enc, wk, bk, (float*)P.Kh, Bb*Ss, Hh, Hh, Hh, 1);
    gemm128_kernel<<<dim3(Hh/128, (Bb*Ss)/128), 256>>>(enc, wv, bv, (float*)P.Vh, Bb*Ss, Hh, Hh, Hh, 0);

    // full 63-step recurrence, 4 flat grid barriers per step
    decoder_loop_kernel<<<NBLK2, 256>>>(P);

    // batched output MLP: o1 = relu(comb @ w_o1^T + b_o1)  (fp32)
    gemm128_kernel<<<dim3(Hh/128, (STEPS*Bb+127)/128), 256>>>(
        P.comb, w_o1, b_o1, o1, STEPS*Bb, Hh, 2*Hh, 2*Hh, 2);
    // split o1 into bf16 hi/lo, then tensor-core vocab GEMM (128x128 tiles)
    conv_split_kernel<<<(STEPS*Bb*Hh+255)/256, 256>>>(o1, ahi, alo, STEPS*Bb*Hh);
    cudaFuncSetAttribute(gemm_mma_vocab, cudaFuncAttributeMaxDynamicSharedMemorySize, VOCAB_SMEM);
    gemm_mma_vocab<<<dim3(Vv/128, 16), 256, VOCAB_SMEM>>>(ahi, alo, whi, wlo, b_o2, out);
}

// round 17
// speedup vs baseline: 1.3880x; 1.0293x over previous
#include <cuda_runtime.h>
#include <cuda_bf16.h>
#include <math.h>

#define Bb 32
#define Tt 64
#define Ss 256
#define Hh 512
#define Ee 256
#define Vv 32000
#define NHh 8
#define STEPS 63
#define NBLK2 296

// ---------------- scratch ----------------------------------------------------
#define O_KH   0
#define O_VH   (O_KH  + Bb*Ss*Hh)
#define O_H0   (O_VH  + Bb*Ss*Hh)
#define O_H1   (O_H0  + Bb*Hh)
#define O_H0P  (O_H1  + Bb*Hh)
#define O_Q    (O_H0P + Bb*Hh)
#define O_CTXR (O_Q   + Bb*Hh)
#define O_GH0  (O_CTXR+ 2*Bb*Hh)
#define O_GH1  (O_GH0 + Bb*3*Hh)
#define O_EG   (O_GH1 + Bb*3*Hh)
#define O_EMBA (O_EG  + STEPS*Bb*Ee)
#define O_GI0E (O_EMBA+ STEPS*Bb*Hh)
#define O_COMB (O_GI0E+ STEPS*Bb*3*Hh)
#define O_O1   (O_COMB+ STEPS*Bb*2*Hh)
#define O_TOTAL (O_O1 + STEPS*Bb*Hh)

__device__ float g_buf[O_TOTAL];
__device__ unsigned g_cnt_arr[64];
__device__ unsigned g_gen_arr[64];
__device__ __nv_bfloat16 g_whi[Vv*Hh];
__device__ __nv_bfloat16 g_wlo[Vv*Hh];
__device__ __nv_bfloat16 g_ahi[STEPS*Bb*Hh];
__device__ __nv_bfloat16 g_alo[STEPS*Bb*Hh];

__device__ __forceinline__ float clip100(float v){ return fminf(fmaxf(v,-100.f),100.f); }
__device__ __forceinline__ float sigm(float x){ return 1.f/(1.f+expf(-x)); }

// ---------------- setup kernels ----------------------------------------------
__global__ void init_kernel(const float* __restrict__ dec, const float* __restrict__ bo,
                            float* h0, float* h1, float* ctxr0){
    int i = blockIdx.x*256 + threadIdx.x;
    if (i < Bb*Hh){
        float v = fminf(fmaxf(dec[i], -10.f), 10.f);
        h0[i] = v; h1[i] = v;
        ctxr0[i] = bo[i & 511];
    }
}

__global__ void reset_kernel(){
    if (threadIdx.x == 0 && blockIdx.x == 0){ g_cnt_arr[0] = 0u; g_gen_arr[0] = 0u; }
}

__global__ void zero_kernel(float* __restrict__ out){
    int i = blockIdx.x*256 + threadIdx.x;
    if (i < Bb*Vv){
        int b = i / Vv, v = i % Vv;
        out[(size_t)b*Tt*Vv + v] = 0.f;
    }
}

__global__ void gather_emb_kernel(const int* __restrict__ tgt,
                                  const float* __restrict__ embt, float* __restrict__ Eg){
    int idx = blockIdx.x*256 + threadIdx.x;
    int row = idx >> 8, e = idx & 255;
    int t = row >> 5, b = row & 31;
    int tok = tgt[b*Tt + t];
    Eg[row*Ee + e] = embt[tok*Ee + e];
}

// fp32 -> bf16 hi/lo split
__global__ void conv_split_kernel(const float* __restrict__ src,
                                  __nv_bfloat16* __restrict__ hi,
                                  __nv_bfloat16* __restrict__ lo, int n){
    int i = blockIdx.x*256 + threadIdx.x;
    if (i < n){
        float v = src[i];
        __nv_bfloat16 h = __float2bfloat16(v);
        hi[i] = h;
        lo[i] = __float2bfloat16(v - __bfloat162float(h));
    }
}

// ---------------- big tiled SGEMM, double-buffered ----------------------------
// mode: 0 plain, 1 clip100, 2 relu;  ldw = row stride of W (>= K)
__global__ void gemm128_kernel(const float* __restrict__ A, const float* __restrict__ W,
                               const float* __restrict__ bias, float* __restrict__ C,
                               int M, int N, int K, int ldw, int mode){
    __shared__ float As[2][8][128];
    __shared__ float Ws[2][8][128];
    const int tid = threadIdx.x;
    const int bm = blockIdx.y * 128;
    const int bn = blockIdx.x * 128;
    const int lrow = tid >> 1;
    const int lk4  = (tid & 1) * 4;
    const int tx = tid & 15, ty = tid >> 4;

    float acc[8][8];
    #pragma unroll
    for (int i=0;i<8;i++)
        #pragma unroll
        for (int j=0;j<8;j++) acc[i][j]=0.f;

    float4 av, wv;
    auto ld = [&](int kb){
        av = make_float4(0.f,0.f,0.f,0.f);
        int ar = bm + lrow;
        if (ar < M) av = *(const float4*)(A + (size_t)ar*K + kb + lk4);
        wv = *(const float4*)(W + (size_t)(bn+lrow)*ldw + kb + lk4);
    };
    auto st = [&](int p){
        As[p][lk4+0][lrow]=av.x; As[p][lk4+1][lrow]=av.y;
        As[p][lk4+2][lrow]=av.z; As[p][lk4+3][lrow]=av.w;
        Ws[p][lk4+0][lrow]=wv.x; Ws[p][lk4+1][lrow]=wv.y;
        Ws[p][lk4+2][lrow]=wv.z; Ws[p][lk4+3][lrow]=wv.w;
    };

    ld(0); st(0);
    __syncthreads();
    int p = 0;
    for (int kb = 0; kb < K; kb += 8){
        if (kb + 8 < K) ld(kb + 8);
        #pragma unroll
        for (int k=0;k<8;k++){
            float4 a0 = *(const float4*)&As[p][k][ty*4];
            float4 a1 = *(const float4*)&As[p][k][64 + ty*4];
            float4 b0 = *(const float4*)&Ws[p][k][tx*4];
            float4 b1 = *(const float4*)&Ws[p][k][64 + tx*4];
            float am[8] = {a0.x,a0.y,a0.z,a0.w, a1.x,a1.y,a1.z,a1.w};
            float bm_[8]= {b0.x,b0.y,b0.z,b0.w, b1.x,b1.y,b1.z,b1.w};
            #pragma unroll
            for (int i=0;i<8;i++)
                #pragma unroll
                for (int j=0;j<8;j++)
                    acc[i][j] += am[i]*bm_[j];
        }
        if (kb + 8 < K) st(p ^ 1);
        __syncthreads();
        p ^= 1;
    }

    #pragma unroll
    for (int i=0;i<8;i++){
        int gm = bm + (i<4 ? ty*4+i : 64 + ty*4 + (i-4));
        if (gm >= M) continue;
        #pragma unroll
        for (int j=0;j<8;j++){
            int gn = bn + (j<4 ? tx*4+j : 64 + tx*4 + (j-4));
            float v = acc[i][j] + bias[gn];
            if (mode==1)      v = clip100(v);
            else if (mode==2) v = fmaxf(v, 0.f);
            C[(size_t)gm*N + gn] = v;
        }
    }
}

// ---------------- split-bf16 tensor-core vocab GEMM (128x128, cp.async) --------
#define MMA_BF16(cc, aa, bb) \
    asm volatile("mma.sync.aligned.m16n8k16.row.col.f32.bf16.bf16.f32 " \
        "{%0,%1,%2,%3},{%4,%5,%6,%7},{%8,%9},{%0,%1,%2,%3};" \
        : "+f"(cc[0]),"+f"(cc[1]),"+f"(cc[2]),"+f"(cc[3]) \
        : "r"(aa[0]),"r"(aa[1]),"r"(aa[2]),"r"(aa[3]), "r"(bb[0]),"r"(bb[1]))

#define VOCAB_SMEM (4*5120*2 + 4*5120*2)

__global__ void __launch_bounds__(256, 2) gemm_mma_vocab(
    const __nv_bfloat16* __restrict__ Ahi, const __nv_bfloat16* __restrict__ Alo,
    const __nv_bfloat16* __restrict__ Whi, const __nv_bfloat16* __restrict__ Wlo,
    const float* __restrict__ bias, float* __restrict__ out)
{
    extern __shared__ __nv_bfloat16 dsm[];
    const unsigned smem_u32 = (unsigned)__cvta_generic_to_shared(dsm);
    const int tid = threadIdx.x;
    const int lane = tid & 31, wid = tid >> 5;
    const int wm = wid & 1, wn = wid >> 1;
    const int g = lane >> 2, tg = lane & 3;
    const int bn = blockIdx.x * 128;
    const int bm = blockIdx.y * 128;

    float c[16][4];
    #pragma unroll
    for (int i=0;i<16;i++){ c[i][0]=0.f; c[i][1]=0.f; c[i][2]=0.f; c[i][3]=0.f; }

    const int row  = tid >> 1;
    const int h16  = (tid & 1) * 16;
    const int apred = ((bm + row) < STEPS*Bb) ? 16 : 0;

    auto cp16 = [&](unsigned dst, const void* src, int sz){
        asm volatile("cp.async.cg.shared.global [%0], [%1], 16, %2;"
                     :: "r"(dst), "l"(src), "r"(sz) : "memory");
    };
    auto cp_chunk = [&](int kb, int st){
        const size_t aoff = (size_t)(bm + row)*512 + kb + h16;
        unsigned da = smem_u32 + ((st*2+0)*5120 + row*40 + h16)*2;
        cp16(da,      Ahi + aoff,     apred);
        cp16(da + 16, Ahi + aoff + 8, apred);
        unsigned dal = da + 5120*2;
        cp16(dal,      Alo + aoff,     apred);
        cp16(dal + 16, Alo + aoff + 8, apred);
        const size_t woff = (size_t)(bn + row)*512 + kb + h16;
        unsigned dw = smem_u32 + (20480 + (st*2+0)*5120 + row*40 + h16)*2;
        cp16(dw,      Whi + woff,     16);
        cp16(dw + 16, Whi + woff + 8, 16);
        unsigned dwl = dw + 5120*2;
        cp16(dwl,      Wlo + woff,     16);
        cp16(dwl + 16, Wlo + woff + 8, 16);
        asm volatile("cp.async.commit_group;");
    };

    cp_chunk(0, 0);
    int st = 0;
    for (int kb = 0; kb < 512; kb += 32){
        if (kb + 32 < 512){
            cp_chunk(kb + 32, st ^ 1);
            asm volatile("cp.async.wait_group 1;");
        } else {
            asm volatile("cp.async.wait_group 0;");
        }
        __syncthreads();
        const __nv_bfloat16* A0 = dsm + (st*2+0)*5120;
        const __nv_bfloat16* A1 = dsm + (st*2+1)*5120;
        const __nv_bfloat16* W0 = dsm + 20480 + (st*2+0)*5120;
        const __nv_bfloat16* W1 = dsm + 20480 + (st*2+1)*5120;
        #pragma unroll
        for (int ko = 0; ko < 32; ko += 16){
            unsigned ah[4][4], al[4][4], bh[4][2], bl[4][2];
            const int c0 = ko + 2*tg, c8 = c0 + 8;
            #pragma unroll
            for (int mt=0; mt<4; mt++){
                int r0 = (wm*64 + mt*16 + g)*40;
                ah[mt][0] = *(const unsigned*)&A0[r0 + c0];
                ah[mt][1] = *(const unsigned*)&A0[r0 + 320 + c0];
                ah[mt][2] = *(const unsigned*)&A0[r0 + c8];
                ah[mt][3] = *(const unsigned*)&A0[r0 + 320 + c8];
                al[mt][0] = *(const unsigned*)&A1[r0 + c0];
                al[mt][1] = *(const unsigned*)&A1[r0 + 320 + c0];
                al[mt][2] = *(const unsigned*)&A1[r0 + c8];
                al[mt][3] = *(const unsigned*)&A1[r0 + 320 + c8];
            }
            #pragma unroll
            for (int nt=0; nt<4; nt++){
                int n0 = (wn*32 + nt*8 + g)*40;
                bh[nt][0] = *(const unsigned*)&W0[n0 + c0];
                bh[nt][1] = *(const unsigned*)&W0[n0 + c8];
                bl[nt][0] = *(const unsigned*)&W1[n0 + c0];
                bl[nt][1] = *(const unsigned*)&W1[n0 + c8];
            }
            #pragma unroll
            for (int mt=0; mt<4; mt++)
                #pragma unroll
                for (int nt=0; nt<4; nt++){
                    MMA_BF16(c[mt*4+nt], ah[mt], bh[nt]);
                    MMA_BF16(c[mt*4+nt], ah[mt], bl[nt]);
                    MMA_BF16(c[mt*4+nt], al[mt], bh[nt]);
                }
        }
        __syncthreads();
        st ^= 1;
    }
    #pragma unroll
    for (int nt=0; nt<4; nt++){
        int col = bn + wn*32 + nt*8 + 2*tg;
        float b0 = bias[col], b1 = bias[col+1];
        #pragma unroll
        for (int mt=0; mt<4; mt++){
            #pragma unroll
            for (int half=0; half<2; half++){
                int gm = bm + wm*64 + mt*16 + g + half*8;
                if (gm >= STEPS*Bb) continue;
                int bb2 = gm & 31, tt2 = gm >> 5;
                float v0 = clip100(c[mt*4+nt][half*2+0] + b0);
                float v1 = clip100(c[mt*4+nt][half*2+1] + b1);
                *(float2*)&out[((size_t)bb2*Tt + tt2 + 1)*Vv + col] = make_float2(v0, v1);
            }
        }
    }
}

// ---------------- persistent decoder loop -------------------------------------
struct SmemG { float As[32*132]; float Ws[32*128]; };
struct SmemA { float qs[64]; float sc[256]; float red[64];
               float psum[4][64]; float ctxv[64]; };
union SmemU { SmemG g; SmemA a; };

struct Params {
    const int* mask;
    const float* wq;   const float* bq;
    const float* wo;   const float* bo;
    const float* w_ih0; const float* w_hh0; const float* b_ih0; const float* b_hh0;
    const float* w_ih1; const float* w_hh1; const float* b_ih1; const float* b_hh1;
    const float* Kh; const float* Vh; const float* gi0e;
    float *h0, *h1, *h0p, *q, *ctxr, *gh0, *gh1, *comb;
};

// flat counter barrier WITHOUT __threadfence (no CCTL.IVALL / L1 flush).
// arrival = release-atomic (orders prior stores to L2); poll = acquire load.
// All mutable inter-block data uses .cg accesses (L2 is coherence point).
__device__ __forceinline__ void grid_bar(unsigned target){
    __syncthreads();
    if (threadIdx.x == 0){
        unsigned prev;
        asm volatile("atom.release.gpu.add.u32 %0, [%1], 1;"
                     : "=r"(prev) : "l"(&g_cnt_arr[0]) : "memory");
        if (prev == target*NBLK2 - 1u){
            asm volatile("st.release.gpu.u32 [%0], %1;" :: "l"(&g_gen_arr[0]), "r"(target) : "memory");
        } else {
            unsigned v;
            do {
                asm volatile("ld.acquire.gpu.u32 %0, [%1];" : "=r"(v) : "l"(&g_gen_arr[0]) : "memory");
            } while (v < target);
        }
    }
    __syncthreads();
}

__device__ __forceinline__ float block_max(float v, float* red){
    #pragma unroll
    for (int off=16; off>0; off>>=1) v = fmaxf(v, __shfl_xor_sync(0xffffffffu, v, off));
    if ((threadIdx.x & 31) == 0) red[threadIdx.x >> 5] = v;
    __syncthreads();
    if (threadIdx.x < 8){
        float x = red[threadIdx.x];
        #pragma unroll
        for (int off=4; off>0; off>>=1) x = fmaxf(x, __shfl_xor_sync(0xffu, x, off));
        if (threadIdx.x == 0) red[0] = x;
    }
    __syncthreads();
    float r = red[0];
    __syncthreads();
    return r;
}
__device__ __forceinline__ float block_sum(float v, float* red){
    #pragma unroll
    for (int off=16; off>0; off>>=1) v += __shfl_xor_sync(0xffffffffu, v, off);
    if ((threadIdx.x & 31) == 0) red[threadIdx.x >> 5] = v;
    __syncthreads();
    if (threadIdx.x < 8){
        float x = red[threadIdx.x];
        #pragma unroll
        for (int off=4; off>0; off>>=1) x += __shfl_xor_sync(0xffu, x, off);
        if (threadIdx.x == 0) red[0] = x;
    }
    __syncthreads();
    float r = red[0];
    __syncthreads();
    return r;
}

// M=32 GEMM; A is MUTABLE (read via .cg), W/bias read-only (L1-resident).
template<int NW>
__device__ void gemm_task(SmemU* sm, int n0, const float* __restrict__ A,
                          int K, const float* __restrict__ W, const float* __restrict__ bias,
                          float* __restrict__ C, int ldc, int act)
{
    const int tid = threadIdx.x;
    const int lane = tid & 31;
    const int wp = tid >> 5;
    float acc[NW];
    #pragma unroll
    for (int i=0;i<NW;i++) acc[i]=0.f;

    float4 pa[4];
    float4 pw[NW];
    auto loadA = [&](int kb){
        #pragma unroll
        for (int p2=0;p2<4;p2++){
            int idx = tid + p2*256;
            int r = idx >> 5, c4 = (idx & 31)*4;
            pa[p2] = __ldcg((const float4*)(A + r*512 + kb + c4));
        }
    };
    auto loadW = [&](int kb){
        #pragma unroll
        for (int q2=0;q2<NW;q2++){
            int idx = tid + q2*256;
            int n = idx >> 5, c4 = (idx & 31)*4;
            pw[q2] = *(const float4*)(W + (size_t)(n0+n)*K + kb + c4);
        }
    };

    loadA(0); loadW(0);
    for (int kb=0; kb<K; kb+=128){
        __syncthreads();
        #pragma unroll
        for (int p2=0;p2<4;p2++){
            int idx = tid + p2*256;
            int r = idx >> 5, c4 = (idx & 31)*4;
            *(float4*)&sm->g.As[r*132 + c4] = pa[p2];
        }
        #pragma unroll
        for (int q2=0;q2<NW;q2++){
            int idx = tid + q2*256;
            int n = idx >> 5, c4 = (idx & 31)*4;
            *(float4*)&sm->g.Ws[n*128 + c4] = pw[q2];
        }
        __syncthreads();
        if (kb + 128 < K){ loadA(kb+128); loadW(kb+128); }
        #pragma unroll
        for (int kc=0; kc<128; kc+=32){
            float a[32];
            #pragma unroll
            for (int j=0;j<32;j+=4)
                *(float4*)&a[j] = *(const float4*)&sm->g.As[lane*132 + kc + j];
            #pragma unroll
            for (int nn=0;nn<NW;nn++){
                const float* wr = &sm->g.Ws[(wp*NW+nn)*128 + kc];
                float s0=0.f, s1=0.f;
                #pragma unroll
                for (int j=0;j<32;j+=8){
                    float4 w0 = *(const float4*)(wr + j);
                    float4 w1 = *(const float4*)(wr + j + 4);
                    s0 += a[j+0]*w0.x + a[j+1]*w0.y + a[j+2]*w0.z + a[j+3]*w0.w;
                    s1 += a[j+4]*w1.x + a[j+5]*w1.y + a[j+6]*w1.z + a[j+7]*w1.w;
                }
                acc[nn] += s0 + s1;
            }
        }
    }
    #pragma unroll
    for (int nn=0;nn<NW;nn++){
        int n = n0 + wp*NW + nn;
        float v = acc[nn] + bias[n];
        if (act) v = clip100(v);
        __stcg(&C[lane*ldc + n], v);
    }
}

// fused GEMM-triplet (K=512) + GRU nonlinearity. A/gh/hstate mutable (.cg).
template<bool CLIPA>
__device__ void gru_task(SmemU* sm, int n0, const float* __restrict__ A,
                         const float* __restrict__ W, int wstride, int woff,
                         const float* __restrict__ pre, const float* __restrict__ b_ih,
                         const float* __restrict__ gh,
                         float* __restrict__ hstate, float* __restrict__ hpre,
                         float* __restrict__ comb, const float* __restrict__ ctxr)
{
    const int tid = threadIdx.x;
    const int lane = tid & 31;
    const int wp = tid >> 5;
    float acc0=0.f, acc1=0.f, acc2=0.f;

    float4 pa[4];
    float4 pw[3];
    auto loadA = [&](int kb){
        #pragma unroll
        for (int p2=0;p2<4;p2++){
            int idx = tid + p2*256;
            int r = idx >> 5, c4 = (idx & 31)*4;
            float4 v = __ldcg((const float4*)(A + r*512 + kb + c4));
            if (CLIPA){
                v.x=clip100(v.x); v.y=clip100(v.y); v.z=clip100(v.z); v.w=clip100(v.w);
            }
            pa[p2] = v;
        }
    };
    auto loadW = [&](int kb){
        #pragma unroll
        for (int q2=0;q2<3;q2++){
            int idx = tid + q2*256;
            int nn = idx >> 5, c4 = (idx & 31)*4;
            int w = nn / 3, g = nn % 3;
            int grow = n0 + w + g*512;
            pw[q2] = *(const float4*)(W + (size_t)grow*wstride + woff + kb + c4);
        }
    };

    loadA(0); loadW(0);
    #pragma unroll
    for (int kb=0; kb<512; kb+=128){
        __syncthreads();
        #pragma unroll
        for (int p2=0;p2<4;p2++){
            int idx = tid + p2*256;
            int r = idx >> 5, c4 = (idx & 31)*4;
            *(float4*)&sm->g.As[r*132 + c4] = pa[p2];
        }
        #pragma unroll
        for (int q2=0;q2<3;q2++){
            int idx = tid + q2*256;
            int nn = idx >> 5, c4 = (idx & 31)*4;
            int w = nn / 3, g = nn % 3;
            *(float4*)&sm->g.Ws[(w*3+g)*128 + c4] = pw[q2];
        }
        __syncthreads();
        if (kb + 128 < 512){ loadA(kb+128); loadW(kb+128); }
        #pragma unroll
        for (int kc=0; kc<128; kc+=32){
            float a[32];
            #pragma unroll
            for (int j=0;j<32;j+=4)
                *(float4*)&a[j] = *(const float4*)&sm->g.As[lane*132 + kc + j];
            #pragma unroll
            for (int g=0; g<3; g++){
                const float* wr = &sm->g.Ws[(wp*3+g)*128 + kc];
                float s0=0.f, s1=0.f;
                #pragma unroll
                for (int j=0;j<32;j+=8){
                    float4 w0 = *(const float4*)(wr + j);
                    float4 w1 = *(const float4*)(wr + j + 4);
                    s0 += a[j+0]*w0.x + a[j+1]*w0.y + a[j+2]*w0.z + a[j+3]*w0.w;
                    s1 += a[j+4]*w1.x + a[j+5]*w1.y + a[j+6]*w1.z + a[j+7]*w1.w;
                }
                float s = s0 + s1;
                if (g==0) acc0 += s; else if (g==1) acc1 += s; else acc2 += s;
            }
        }
    }
    const int j = n0 + wp, b = lane;
    float pv0, pv1, pv2;
    if (pre){
        pv0 = pre[b*1536 + j];
        pv1 = pre[b*1536 + j + 512];
        pv2 = pre[b*1536 + j + 1024];
    } else {
        pv0 = b_ih[j]; pv1 = b_ih[j+512]; pv2 = b_ih[j+1024];
    }
    float ir = acc0 + pv0;
    float iz = acc1 + pv1;
    float in_ = acc2 + pv2;
    const int gg = b*1536 + j;
    float r = sigm(ir + __ldcg(&gh[gg]));
    float z = sigm(iz + __ldcg(&gh[gg+512]));
    float n = tanhf(in_ + r*__ldcg(&gh[gg+1024]));
    float hv = (1.f - z)*n + z*__ldcg(&hstate[b*512 + j]);
    if (hpre) __stcg(&hpre[b*512 + j], hv);
    __stcg(&hstate[b*512 + j], fminf(fmaxf(hv, -10.f), 10.f));
    if (comb){
        __stcg(&comb[b*1024 + j], hv);
        __stcg(&comb[b*1024 + 512 + j], clip100(__ldcg(&ctxr[b*512 + j])));
    }
}

// attention core for (head h, single batch b); q mutable (.cg), K/V/wo read-only
__device__ void attn_core(SmemU* smu, const Params& P, int h, int b, float* ctxr){
    SmemA* sa = &smu->a;
    const int tid = threadIdx.x;
    if (tid < 64) sa->qs[tid] = __ldcg(&P.q[b*512 + h*64 + tid]);
    __syncthreads();

    const float* kp = P.Kh + ((size_t)(b*256 + tid))*512 + h*64;
    float s = 0.f;
    #pragma unroll
    for (int d=0; d<64; d+=4){
        float4 kv = *(const float4*)(kp + d);
        s += sa->qs[d]*kv.x + sa->qs[d+1]*kv.y + sa->qs[d+2]*kv.z + sa->qs[d+3]*kv.w;
    }
    s *= 0.125f;
    if (P.mask[b*256 + tid] == 0) s = -10000.f;
    float mx = block_max(s, sa->red);
    float e = expf(s - mx);
    sa->sc[tid] = e;
    float inv = 1.f / block_sum(e, sa->red);
    __syncthreads();
    {
        int d = tid & 63, part = tid >> 6;
        const float* vp = P.Vh + ((size_t)(b*256))*512 + h*64 + d;
        float p[16];
        #pragma unroll
        for (int i=0;i<16;i++) p[i]=0.f;
        #pragma unroll
        for (int o=0;o<4;o++){
            int s2 = part*64 + o*16;
            #pragma unroll
            for (int i=0;i<16;i++)
                p[i] += sa->sc[s2+i] * vp[(size_t)(s2+i)*512];
        }
        float r0 = ((p[0]+p[1])+(p[2]+p[3])) + ((p[4]+p[5])+(p[6]+p[7]));
        float r1 = ((p[8]+p[9])+(p[10]+p[11])) + ((p[12]+p[13])+(p[14]+p[15]));
        sa->psum[part][d] = r0 + r1;
    }
    __syncthreads();
    if (tid < 64)
        sa->ctxv[tid] = (sa->psum[0][tid]+sa->psum[1][tid]
                       + sa->psum[2][tid]+sa->psum[3][tid]) * inv;
    __syncthreads();
    #pragma unroll
    for (int rr=0; rr<2; rr++){
        int n = tid + rr*256;
        const float4* wr = (const float4*)(P.wo + (size_t)n*512 + h*64);
        float s0=0.f;
        #pragma unroll
        for (int j=0;j<16;j++){
            float4 w = wr[j];
            const float* c0 = &sa->ctxv[j*4];
            s0 += c0[0]*w.x + c0[1]*w.y + c0[2]*w.z + c0[3]*w.w;
        }
        atomicAdd(ctxr + b*512 + n, s0);
    }
}

#define PHASE(nt_, ...)                                               \
    for (int ti = (int)blockIdx.x; ti < (nt_); ti += NBLK2){          \
        __syncthreads();                                              \
        __VA_ARGS__                                                   \
    }                                                                 \
    bar++; grid_bar(bar);

__global__ void __launch_bounds__(256, 2) decoder_loop_kernel(Params P){
    __shared__ SmemU sm;
    const int tid = threadIdx.x;
    unsigned bar = 0;

    for (int t = 0; t < STEPS; t++){
        float* ctxc = P.ctxr + (t & 1)*Bb*Hh;

        // P1: qproj x32 + gh1 x96 + gh0 x96 + ctx-init x8  (232 tasks)
        PHASE(232, {
            if (ti < 32){
                gemm_task<2>(&sm, ti*16, P.h1, 512, P.wq, P.bq, P.q, 512, 1);
            } else if (ti < 128){
                gemm_task<2>(&sm, (ti-32)*16, P.h1, 512, P.w_hh1, P.b_hh1, P.gh1, 1536, 0);
            } else if (ti < 224){
                gemm_task<2>(&sm, (ti-128)*16, P.h0, 512, P.w_hh0, P.b_hh0, P.gh0, 1536, 0);
            } else {
                int base = (ti-224)*2048 + tid;
                #pragma unroll
                for (int e=0;e<8;e++){
                    int idx = base + e*256;
                    __stcg(&ctxc[idx], P.bo[idx & 511]);
                }
            }
        })
        // P2: attention only, (h, b) x256 tasks
        PHASE(256, {
            attn_core(&sm, P, ti >> 5, ti & 31, ctxc);
        })
        // P3: gi0(ctx half, K=512) + GRU0 fused  (64 tasks)
        PHASE(64, {
            gru_task<true>(&sm, ti*8, ctxc, P.w_ih0, 1024, 512,
                           P.gi0e + (size_t)t*Bb*3*Hh, nullptr,
                           P.gh0, P.h0, P.h0p, nullptr, nullptr);
        })
        // P4: gi1(K=512) + GRU1 fused + comb store  (64 tasks)
        PHASE(64, {
            gru_task<false>(&sm, ti*8, P.h0p, P.w_ih1, 512, 0,
                            nullptr, P.b_ih1,
                            P.gh1, P.h1, nullptr,
                            P.comb + (size_t)t*Bb*2*Hh, ctxc);
        })
    }
}

// ---------------- driver -------------------------------------------------------
extern "C" void kernel_launch(void* const* d_in, const int* in_sizes, int n_in,
                              void* d_out, int out_size){
    const int*   tgt   = (const int*)  d_in[0];
    const float* enc   = (const float*)d_in[1];
    const float* dec   = (const float*)d_in[2];
    const int*   mask  = (const int*)  d_in[3];
    const float* embt  = (const float*)d_in[4];
    const float* w_ep  = (const float*)d_in[5];
    const float* b_ep  = (const float*)d_in[6];
    const float* wq    = (const float*)d_in[7];
    const float* bq    = (const float*)d_in[8];
    const float* wk    = (const float*)d_in[9];
    const float* bk    = (const float*)d_in[10];
    const float* wv    = (const float*)d_in[11];
    const float* bv    = (const float*)d_in[12];
    const float* wo    = (const float*)d_in[13];
    const float* bo    = (const float*)d_in[14];
    const float* w_ih0 = (const float*)d_in[15];
    const float* w_hh0 = (const float*)d_in[16];
    const float* b_ih0 = (const float*)d_in[17];
    const float* b_hh0 = (const float*)d_in[18];
    const float* w_ih1 = (const float*)d_in[19];
    const float* w_hh1 = (const float*)d_in[20];
    const float* b_ih1 = (const float*)d_in[21];
    const float* b_hh1 = (const float*)d_in[22];
    const float* w_o1  = (const float*)d_in[23];
    const float* b_o1  = (const float*)d_in[24];
    const float* w_o2  = (const float*)d_in[25];
    const float* b_o2  = (const float*)d_in[26];
    float* out = (float*)d_out;

    float* buf = nullptr;
    cudaGetSymbolAddress((void**)&buf, g_buf);
    __nv_bfloat16 *whi, *wlo, *ahi, *alo;
    cudaGetSymbolAddress((void**)&whi, g_whi);
    cudaGetSymbolAddress((void**)&wlo, g_wlo);
    cudaGetSymbolAddress((void**)&ahi, g_ahi);
    cudaGetSymbolAddress((void**)&alo, g_alo);

    Params P;
    P.mask = mask;
    P.wq = wq; P.bq = bq; P.wo = wo; P.bo = bo;
    P.w_ih0 = w_ih0; P.w_hh0 = w_hh0; P.b_ih0 = b_ih0; P.b_hh0 = b_hh0;
    P.w_ih1 = w_ih1; P.w_hh1 = w_hh1; P.b_ih1 = b_ih1; P.b_hh1 = b_hh1;
    P.Kh = buf + O_KH; P.Vh = buf + O_VH;
    P.h0 = buf + O_H0; P.h1 = buf + O_H1; P.h0p = buf + O_H0P;
    P.q = buf + O_Q; P.ctxr = buf + O_CTXR;
    P.gh0 = buf + O_GH0; P.gh1 = buf + O_GH1;
    P.gi0e = buf + O_GI0E;
    P.comb = buf + O_COMB;
    float* Eg = buf + O_EG;
    float* emba = buf + O_EMBA;
    float* o1 = buf + O_O1;

    reset_kernel<<<1, 32>>>();
    init_kernel<<<(Bb*Hh+255)/256, 256>>>(dec, bo, P.h0, P.h1, P.ctxr);
    zero_kernel<<<(Bb*Vv+255)/256, 256>>>(out);

    // one-time: split w_o2 into bf16 hi/lo
    conv_split_kernel<<<(Vv*Hh+255)/256, 256>>>(w_o2, whi, wlo, Vv*Hh);

    // hoisted: embedding gather + projection for all 63 steps
    gather_emb_kernel<<<(STEPS*Bb*Ee)/256, 256>>>(tgt, embt, Eg);
    gemm128_kernel<<<dim3(Hh/128, (STEPS*Bb+127)/128), 256>>>(
        Eg, w_ep, b_ep, emba, STEPS*Bb, Hh, Ee, Ee, 0);
    // hoisted: emb half of gi0 for all steps
    gemm128_kernel<<<dim3((3*Hh)/128, (STEPS*Bb+127)/128), 256>>>(
        emba, w_ih0, b_ih0, (float*)P.gi0e, STEPS*Bb, 3*Hh, Hh, 2*Hh, 0);

    // step-invariant K/V projections (Kh clipped, Vh plain)
    gemm128_kernel<<<dim3(Hh/128, (Bb*Ss)/128), 256>>>(enc, wk, bk, (float*)P.Kh, Bb*Ss, Hh, Hh, Hh, 1);
    gemm128_kernel<<<dim3(Hh/128, (Bb*Ss)/128), 256>>>(enc, wv, bv, (float*)P.Vh, Bb*Ss, Hh, Hh, Hh, 0);

    // full 63-step recurrence, 4 fence-free grid barriers per step
    decoder_loop_kernel<<<NBLK2, 256>>>(P);

    // batched output MLP: o1 = relu(comb @ w_o1^T + b_o1)  (fp32)
    gemm128_kernel<<<dim3(Hh/128, (STEPS*Bb+127)/128), 256>>>(
        P.comb, w_o1, b_o1, o1, STEPS*Bb, Hh, 2*Hh, 2*Hh, 2);
    // split o1 into bf16 hi/lo, then tensor-core vocab GEMM (128x128 tiles)
    conv_split_kernel<<<(STEPS*Bb*Hh+255)/256, 256>>>(o1, ahi, alo, STEPS*Bb*Hh);
    cudaFuncSetAttribute(gemm_mma_vocab, cudaFuncAttributeMaxDynamicSharedMemorySize, VOCAB_SMEM);
    gemm_mma_vocab<<<dim3(Vv/128, 16), 256, VOCAB_SMEM>>>(ahi, alo, whi, wlo, b_o2, out);
}